// round 7
// baseline (speedup 1.0000x reference)
#include <cuda_runtime.h>
#include <cuda_fp16.h>
#include <cstdint>
#include <math.h>

#define S_LEN 2048
#define D_MOD 1024
#define ROWS  4096          // B*S
#define NBH   32            // B*H

// ---------------- scratch (static; no allocations) ----------
__device__ __align__(128) __half g_xh [ROWS * D_MOD];
__device__ __align__(128) __half g_Wh [3 * D_MOD * D_MOD];    // [3072][1024] K-major fp16
__device__ __align__(128) __half g_Woh[D_MOD * D_MOD];
__device__ __align__(128) __half g_Q  [NBH * S_LEN * 64];
__device__ __align__(128) __half g_K  [NBH * S_LEN * 64];
__device__ __align__(128) __half g_V  [NBH * S_LEN * 64];
__device__ __align__(128) __half g_Vt [NBH * 64 * S_LEN];     // [bh][dk][s]
__device__ __align__(128) __half g_ctxh[ROWS * D_MOD];
__device__ __align__(128) float  g_prj[ROWS * D_MOD];

// ---------------- helpers ----------------
__device__ __forceinline__ uint32_t smem_u32(const void* p) {
    uint32_t a;
    asm("{ .reg .u64 t; cvta.to.shared.u64 t, %1; cvt.u32.u64 %0, t; }" : "=r"(a) : "l"(p));
    return a;
}
__device__ __forceinline__ void cp16(uint32_t dst, const void* src) {
    asm volatile("cp.async.cg.shared.global [%0], [%1], 16;" :: "r"(dst), "l"(src) : "memory");
}
#define CP_COMMIT() asm volatile("cp.async.commit_group;" ::: "memory")
#define CP_WAIT0()  asm volatile("cp.async.wait_group 0;" ::: "memory")
#define CP_WAIT1()  asm volatile("cp.async.wait_group 1;" ::: "memory")

__device__ __forceinline__ void mma16(float* d, const uint32_t* a, uint32_t b0, uint32_t b1) {
    asm volatile("mma.sync.aligned.m16n8k16.row.col.f32.f16.f16.f32 "
        "{%0,%1,%2,%3}, {%4,%5,%6,%7}, {%8,%9}, {%0,%1,%2,%3};"
        : "+f"(d[0]), "+f"(d[1]), "+f"(d[2]), "+f"(d[3])
        : "r"(a[0]), "r"(a[1]), "r"(a[2]), "r"(a[3]), "r"(b0), "r"(b1));
}
__device__ __forceinline__ void ldsm4(uint32_t& r0, uint32_t& r1, uint32_t& r2, uint32_t& r3,
                                      uint32_t addr) {
    asm volatile("ldmatrix.sync.aligned.m8n8.x4.shared.b16 {%0,%1,%2,%3}, [%4];"
        : "=r"(r0), "=r"(r1), "=r"(r2), "=r"(r3) : "r"(addr));
}

// ======================= fp16 mma.sync GEMM =======================
// C[4096, N] = A[4096,1024] @ W[N,1024]^T + bias.  BM=BN=128, BK=32 halves.
#define GPAD 20

template <int QKV>
__global__ __launch_bounds__(256, 2) void gemm_h(
    const __half* __restrict__ A, const __half* __restrict__ W,
    const float* __restrict__ b0, const float* __restrict__ b1, const float* __restrict__ b2,
    __half* __restrict__ hq, __half* __restrict__ hk, __half* __restrict__ hv,
    float* __restrict__ of)
{
    __shared__ uint32_t As[2][128 * GPAD];
    __shared__ uint32_t Bs[2][128 * GPAD];

    const int tid = threadIdx.x;
    const int wid = tid >> 5, lane = tid & 31;
    const int g = lane >> 2, t = lane & 3;
    const int wm = wid & 1, wn = wid >> 1;       // warp 64 (M) x 32 (N)
    const int m0 = blockIdx.y * 128;
    const int n0 = blockIdx.x * 128;

    // ldmatrix per-thread offsets
    const int lrow  = (lane & 7) + ((lane >> 3) & 1) * 8;
    const int lcol4 = (lane >> 4) * 4;

    const uint32_t sA[2] = {smem_u32(As[0]), smem_u32(As[1])};
    const uint32_t sB[2] = {smem_u32(Bs[0]), smem_u32(Bs[1])};

    float acc[4][4][4];
#pragma unroll
    for (int i = 0; i < 4; i++)
#pragma unroll
        for (int j = 0; j < 4; j++)
#pragma unroll
            for (int r = 0; r < 4; r++) acc[i][j][r] = 0.f;

#define G_LOAD(st, kt) do {                                                       \
    _Pragma("unroll")                                                             \
    for (int i = 0; i < 2; i++) {                                                 \
        int j = tid + i * 256;                                                    \
        int r = j >> 2, cq = j & 3;                                               \
        cp16(sA[st] + (uint32_t)(r * GPAD + cq * 4) * 4,                          \
             A + (size_t)(m0 + r) * 1024 + (kt) * 32 + cq * 8);                   \
        cp16(sB[st] + (uint32_t)(r * GPAD + cq * 4) * 4,                          \
             W + (size_t)(n0 + r) * 1024 + (kt) * 32 + cq * 8);                   \
    }                                                                             \
    CP_COMMIT();                                                                  \
} while (0)

    G_LOAD(0, 0);
    for (int kt = 0; kt < 32; kt++) {
        const int st = kt & 1;
        if (kt < 31) { G_LOAD(st ^ 1, kt + 1); CP_WAIT1(); }
        else         { CP_WAIT0(); }
        __syncthreads();

#pragma unroll
        for (int ks = 0; ks < 2; ks++) {
            uint32_t af[4][4];
#pragma unroll
            for (int mt = 0; mt < 4; mt++)
                ldsm4(af[mt][0], af[mt][1], af[mt][2], af[mt][3],
                      sA[st] + 4u * ((wm * 64 + mt * 16 + lrow) * GPAD + ks * 8 + lcol4));
#pragma unroll
            for (int np = 0; np < 2; np++) {
                uint32_t r0, r1, r2, r3;
                ldsm4(r0, r1, r2, r3,
                      sB[st] + 4u * ((wn * 32 + np * 16 + lrow) * GPAD + ks * 8 + lcol4));
#pragma unroll
                for (int mt = 0; mt < 4; mt++) {
                    mma16(acc[mt][2 * np],     af[mt], r0, r2);
                    mma16(acc[mt][2 * np + 1], af[mt], r1, r3);
                }
            }
        }
        __syncthreads();
    }

    // epilogue
#pragma unroll
    for (int mt = 0; mt < 4; mt++) {
        const int r0 = m0 + wm * 64 + mt * 16 + g;
#pragma unroll
        for (int nt = 0; nt < 4; nt++) {
            const int col = n0 + wn * 32 + nt * 8 + 2 * t;
            if (QKV) {
                const int mat = col >> 10, nl = col & 1023;
                const float* bias = (mat == 0 ? b0 : mat == 1 ? b1 : b2);
                __half* op = (mat == 0 ? hq : mat == 1 ? hk : hv);
                const int h = nl >> 6, d = nl & 63;
                const float2 bv = *(const float2*)(bias + nl);
                const int b = r0 >> 11, s = r0 & 2047;
                __half* p = op + ((size_t)((b * 16 + h) * 2048 + s)) * 64 + d;
                *(__half2*)p = __floats2half2_rn(acc[mt][nt][0] + bv.x, acc[mt][nt][1] + bv.y);
                *(__half2*)(p + 8 * 64) = __floats2half2_rn(acc[mt][nt][2] + bv.x,
                                                            acc[mt][nt][3] + bv.y);
            } else {
                const float2 bv = *(const float2*)(b0 + col);
                float* p = of + (size_t)r0 * 1024 + col;
                *(float2*)p = make_float2(acc[mt][nt][0] + bv.x, acc[mt][nt][1] + bv.y);
                *(float2*)(p + 8 * 1024) = make_float2(acc[mt][nt][2] + bv.x,
                                                       acc[mt][nt][3] + bv.y);
            }
        }
    }
}

// ======================= fp16 flash attention =======================
// CTA: 128 queries, 8 warps (16 q-rows each). KV tiles of 64 keys.
#define AP   36
#define QU   (128 * AP)
#define KVU  (64 * AP)
#define ATTN_SMEM ((QU + 4 * KVU) * 4)   // 55296 bytes

__global__ __launch_bounds__(256, 2) void attn_h(
    const __half* __restrict__ Q, const __half* __restrict__ K,
    const __half* __restrict__ Vt, __half* __restrict__ Ctx)
{
    extern __shared__ uint32_t smu[];
    uint32_t* Qs = smu;
    uint32_t* Ks = smu + QU;
    uint32_t* Vs = smu + QU + 2 * KVU;

    const int bh = blockIdx.y;
    const int q0 = blockIdx.x * 128;
    const int tid = threadIdx.x;
    const int wid = tid >> 5, lane = tid & 31;
    const int g = lane >> 2, t = lane & 3;
    const int lrow  = (lane & 7) + ((lane >> 3) & 1) * 8;
    const int lcol4 = (lane >> 4) * 4;

    const __half* Qb = Q  + (size_t)bh * S_LEN * 64;
    const __half* Kb = K  + (size_t)bh * S_LEN * 64;
    const __half* Vb = Vt + (size_t)bh * 64 * S_LEN;

    const uint32_t uQ = smem_u32(Qs);
    const uint32_t uK[2] = {smem_u32(Ks), smem_u32(Ks + KVU)};
    const uint32_t uV[2] = {smem_u32(Vs), smem_u32(Vs + KVU)};

#define LOAD_K(st, kt) do { _Pragma("unroll") for (int i = 0; i < 2; i++) { \
    int j = tid + i * 256; int r = j >> 3, cq = j & 7;                      \
    cp16(uK[st] + (uint32_t)(r * AP + cq * 4) * 4,                          \
         Kb + (size_t)((kt) * 64 + r) * 64 + cq * 8); } } while (0)
#define LOAD_V(st, kt) do { _Pragma("unroll") for (int i = 0; i < 2; i++) { \
    int j = tid + i * 256; int r = j >> 3, cq = j & 7;                      \
    cp16(uV[st] + (uint32_t)(r * AP + cq * 4) * 4,                          \
         Vb + (size_t)r * S_LEN + (kt) * 64 + cq * 8); } } while (0)

    // prologue: Q + K0 + V0
#pragma unroll
    for (int i = 0; i < 4; i++) {
        int j = tid + i * 256; int r = j >> 3, cq = j & 7;
        cp16(uQ + (uint32_t)(r * AP + cq * 4) * 4, Qb + (size_t)(q0 + r) * 64 + cq * 8);
    }
    LOAD_K(0, 0); LOAD_V(0, 0); CP_COMMIT();
    CP_WAIT0();
    __syncthreads();

    const int rbase = wid * 16 + g;

    // hoist Q fragments (dk=64 → 4 k16 steps) via ldmatrix
    uint32_t qf[4][4];
#pragma unroll
    for (int ks = 0; ks < 4; ks++)
        ldsm4(qf[ks][0], qf[ks][1], qf[ks][2], qf[ks][3],
              uQ + 4u * ((wid * 16 + lrow) * AP + ks * 8 + lcol4));
    __syncthreads();
    uint32_t* Ps = Qs;                        // Q smem dead; reuse as P buffer
    const uint32_t uP = uQ;

    float m0 = -1e30f, m1 = -1e30f, l0 = 0.f, l1 = 0.f;
    float oacc[8][4];
#pragma unroll
    for (int i = 0; i < 8; i++)
#pragma unroll
        for (int r = 0; r < 4; r++) oacc[i][r] = 0.f;

    for (int kt = 0; kt < 32; kt++) {
        const int st = kt & 1;
        if (kt > 0) { CP_WAIT0(); __syncthreads(); }
        if (kt < 31) { LOAD_K(st ^ 1, kt + 1); LOAD_V(st ^ 1, kt + 1); CP_COMMIT(); }

        // ---- S = Q @ K^T over dk=64 ----
        float sacc[8][4];
#pragma unroll
        for (int i = 0; i < 8; i++)
#pragma unroll
            for (int r = 0; r < 4; r++) sacc[i][r] = 0.f;

#pragma unroll
        for (int ks = 0; ks < 4; ks++) {
#pragma unroll
            for (int np = 0; np < 4; np++) {
                uint32_t r0, r1, r2, r3;
                ldsm4(r0, r1, r2, r3,
                      uK[st] + 4u * ((np * 16 + lrow) * AP + ks * 8 + lcol4));
                mma16(sacc[2 * np],     qf[ks], r0, r2);
                mma16(sacc[2 * np + 1], qf[ks], r1, r3);
            }
        }

        // ---- online softmax (rows rbase, rbase+8) ----
        float rmax0 = -1e30f, rmax1 = -1e30f;
#pragma unroll
        for (int nt = 0; nt < 8; nt++) {
#pragma unroll
            for (int r = 0; r < 4; r++) sacc[nt][r] *= 0.125f;
            rmax0 = fmaxf(rmax0, fmaxf(sacc[nt][0], sacc[nt][1]));
            rmax1 = fmaxf(rmax1, fmaxf(sacc[nt][2], sacc[nt][3]));
        }
        rmax0 = fmaxf(rmax0, __shfl_xor_sync(0xffffffffu, rmax0, 1));
        rmax0 = fmaxf(rmax0, __shfl_xor_sync(0xffffffffu, rmax0, 2));
        rmax1 = fmaxf(rmax1, __shfl_xor_sync(0xffffffffu, rmax1, 1));
        rmax1 = fmaxf(rmax1, __shfl_xor_sync(0xffffffffu, rmax1, 2));

        const float mn0 = fmaxf(m0, rmax0), mn1 = fmaxf(m1, rmax1);
        const float f0 = __expf(m0 - mn0), f1 = __expf(m1 - mn1);
        m0 = mn0; m1 = mn1;

        float rs0 = 0.f, rs1 = 0.f;
#pragma unroll
        for (int nt = 0; nt < 8; nt++) {
            __half2 p0 = __floats2half2_rn(__expf(sacc[nt][0] - m0), __expf(sacc[nt][1] - m0));
            __half2 p1 = __floats2half2_rn(__expf(sacc[nt][2] - m1), __expf(sacc[nt][3] - m1));
            *(__half2*)&Ps[rbase * AP + nt * 4 + t]       = p0;
            *(__half2*)&Ps[(rbase + 8) * AP + nt * 4 + t] = p1;
            const float2 q0f = __half22float2(p0), q1f = __half22float2(p1);
            rs0 += q0f.x + q0f.y; rs1 += q1f.x + q1f.y;
        }
        rs0 += __shfl_xor_sync(0xffffffffu, rs0, 1);
        rs0 += __shfl_xor_sync(0xffffffffu, rs0, 2);
        rs1 += __shfl_xor_sync(0xffffffffu, rs1, 1);
        rs1 += __shfl_xor_sync(0xffffffffu, rs1, 2);
        l0 = l0 * f0 + rs0; l1 = l1 * f1 + rs1;

#pragma unroll
        for (int nt = 0; nt < 8; nt++) {
            oacc[nt][0] *= f0; oacc[nt][1] *= f0;
            oacc[nt][2] *= f1; oacc[nt][3] *= f1;
        }
        __syncwarp();   // Ps rows are per-warp private

        // ---- O += P @ V  (V^T tile: [dk][key]) ----
#pragma unroll
        for (int ks = 0; ks < 4; ks++) {
            uint32_t af[4];
            ldsm4(af[0], af[1], af[2], af[3],
                  uP + 4u * ((wid * 16 + lrow) * AP + ks * 8 + lcol4));
#pragma unroll
            for (int np = 0; np < 4; np++) {
                uint32_t r0, r1, r2, r3;
                ldsm4(r0, r1, r2, r3,
                      uV[st] + 4u * ((np * 16 + lrow) * AP + ks * 8 + lcol4));
                mma16(oacc[2 * np],     af, r0, r2);
                mma16(oacc[2 * np + 1], af, r1, r3);
            }
        }
        __syncwarp();
    }

    // ---- epilogue ----
    const float inv0 = 1.f / l0, inv1 = 1.f / l1;
    const int b = bh >> 4, h = bh & 15;
    const int row0 = q0 + rbase;
    __half* base0 = Ctx + ((size_t)(b * 2048 + row0)) * 1024 + h * 64;
#pragma unroll
    for (int nt = 0; nt < 8; nt++) {
        const int col = nt * 8 + 2 * t;
        *(__half2*)(base0 + col) = __floats2half2_rn(oacc[nt][0] * inv0, oacc[nt][1] * inv0);
        *(__half2*)(base0 + 8 * 1024 + col) = __floats2half2_rn(oacc[nt][2] * inv1,
                                                                oacc[nt][3] * inv1);
    }
}

// ======================= prep kernels =======================
__global__ __launch_bounds__(256) void cvt_x(const float* __restrict__ x,
                                             __half* __restrict__ xh) {
    const int i = blockIdx.x * 256 + threadIdx.x;
    float4 v = ((const float4*)x)[i];
    ((__half2*)xh)[i * 2]     = __floats2half2_rn(v.x, v.y);
    ((__half2*)xh)[i * 2 + 1] = __floats2half2_rn(v.z, v.w);
}

__global__ __launch_bounds__(256) void prep_weights(
    const float* __restrict__ Wq, const float* __restrict__ Wk,
    const float* __restrict__ Wv, const float* __restrict__ Wo,
    __half* __restrict__ Wh, __half* __restrict__ Woh)
{
    __shared__ float tb[32][33];
    const int z = blockIdx.z;
    const float* src = (z == 0) ? Wq : (z == 1) ? Wk : (z == 2) ? Wv : Wo;
    __half* dst = (z < 3) ? (Wh + (size_t)z * D_MOD * D_MOD) : Woh;
    const int k0 = blockIdx.x * 32, n0 = blockIdx.y * 32;
    const int tx = threadIdx.x, ty = threadIdx.y;   // 32 x 8
#pragma unroll
    for (int i = 0; i < 4; i++)
        tb[ty + i * 8][tx] = src[(size_t)(k0 + ty + i * 8) * D_MOD + n0 + tx];
    __syncthreads();
#pragma unroll
    for (int i = 0; i < 4; i++)
        dst[(size_t)(n0 + ty + i * 8) * D_MOD + k0 + tx] = __float2half_rn(tb[tx][ty + i * 8]);
}

// V [bh][s][64] -> Vt [bh][64][s], fp16
__global__ __launch_bounds__(256) void transpose_v(const __half* __restrict__ V,
                                                   __half* __restrict__ Vt) {
    __shared__ __half tb[32][36];
    const int bh = blockIdx.z;
    const int s0 = blockIdx.x * 32, d0 = blockIdx.y * 32;
    const int tx = threadIdx.x, ty = threadIdx.y;   // 32 x 8
    const __half* src = V + (size_t)bh * S_LEN * 64;
    __half* dst = Vt + (size_t)bh * 64 * S_LEN;
#pragma unroll
    for (int i = 0; i < 4; i++)
        tb[ty + i * 8][tx] = src[(size_t)(s0 + ty + i * 8) * 64 + d0 + tx];
    __syncthreads();
#pragma unroll
    for (int i = 0; i < 4; i++)
        dst[(size_t)(d0 + ty + i * 8) * S_LEN + s0 + tx] = tb[tx][ty + i * 8];
}

// ---------------- residual + LayerNorm ------------------------------------
__global__ __launch_bounds__(256) void ln_kernel(
    const float* __restrict__ x, const float* __restrict__ prj,
    const float* __restrict__ gamma, const float* __restrict__ beta,
    float* __restrict__ out)
{
    const int row = blockIdx.x;
    const int tid = threadIdx.x;

    const float4 xv = ((const float4*)(x   + (size_t)row * D_MOD))[tid];
    const float4 pv = ((const float4*)(prj + (size_t)row * D_MOD))[tid];
    float4 h;
    h.x = xv.x + pv.x; h.y = xv.y + pv.y; h.z = xv.z + pv.z; h.w = xv.w + pv.w;

    float sum = h.x + h.y + h.z + h.w;
    float ssq = h.x * h.x + h.y * h.y + h.z * h.z + h.w * h.w;
#pragma unroll
    for (int o = 16; o > 0; o >>= 1) {
        sum += __shfl_xor_sync(0xffffffffu, sum, o);
        ssq += __shfl_xor_sync(0xffffffffu, ssq, o);
    }
    __shared__ float rs[8], rq[8];
    const int warp = tid >> 5, lane = tid & 31;
    if (lane == 0) { rs[warp] = sum; rq[warp] = ssq; }
    __syncthreads();
    float ts = 0.f, tq = 0.f;
#pragma unroll
    for (int i = 0; i < 8; i++) { ts += rs[i]; tq += rq[i]; }

    const float mu   = ts * (1.f / (float)D_MOD);
    const float var  = tq * (1.f / (float)D_MOD) - mu * mu;
    const float rstd = rsqrtf(var + 1e-5f);

    const float4 gg = ((const float4*)gamma)[tid];
    const float4 bb = ((const float4*)beta)[tid];
    float4 o;
    o.x = (h.x - mu) * rstd * gg.x + bb.x;
    o.y = (h.y - mu) * rstd * gg.y + bb.y;
    o.z = (h.z - mu) * rstd * gg.z + bb.z;
    o.w = (h.w - mu) * rstd * gg.w + bb.w;
    ((float4*)(out + (size_t)row * D_MOD))[tid] = o;
}

// ---------------- launch ----------------------------------------------------
extern "C" void kernel_launch(void* const* d_in, const int* in_sizes, int n_in,
                              void* d_out, int out_size)
{
    const float* x  = (const float*)d_in[0];
    const float* Wq = (const float*)d_in[1];
    const float* bq = (const float*)d_in[2];
    const float* Wk = (const float*)d_in[3];
    const float* bk = (const float*)d_in[4];
    const float* Wv = (const float*)d_in[5];
    const float* bv = (const float*)d_in[6];
    const float* Wo = (const float*)d_in[7];
    const float* bo = (const float*)d_in[8];
    const float* ga = (const float*)d_in[9];
    const float* be = (const float*)d_in[10];
    float* out = (float*)d_out;

    __half *Xh, *Wh, *Woh, *Qp, *Kp, *Vp, *Vtp, *Ch;
    float *Pp;
    cudaGetSymbolAddress((void**)&Xh,  g_xh);
    cudaGetSymbolAddress((void**)&Wh,  g_Wh);
    cudaGetSymbolAddress((void**)&Woh, g_Woh);
    cudaGetSymbolAddress((void**)&Qp,  g_Q);
    cudaGetSymbolAddress((void**)&Kp,  g_K);
    cudaGetSymbolAddress((void**)&Vp,  g_V);
    cudaGetSymbolAddress((void**)&Vtp, g_Vt);
    cudaGetSymbolAddress((void**)&Ch,  g_ctxh);
    cudaGetSymbolAddress((void**)&Pp,  g_prj);

    cudaFuncSetAttribute(attn_h, cudaFuncAttributeMaxDynamicSharedMemorySize, ATTN_SMEM);

    cvt_x<<<ROWS * D_MOD / 1024, 256>>>(x, Xh);
    prep_weights<<<dim3(32, 32, 4), dim3(32, 8)>>>(Wq, Wk, Wv, Wo, Wh, Woh);

    gemm_h<1><<<dim3(24, 32), 256>>>(Xh, Wh, bq, bk, bv, Qp, Kp, Vp, nullptr);

    transpose_v<<<dim3(64, 2, NBH), dim3(32, 8)>>>(Vp, Vtp);

    attn_h<<<dim3(S_LEN / 128, NBH), 256, ATTN_SMEM>>>(Qp, Kp, Vtp, Ch);

    gemm_h<0><<<dim3(8, 32), 256>>>(Ch, Woh, bo, bo, bo, nullptr, nullptr, nullptr, Pp);

    ln_kernel<<<ROWS, 256>>>(x, Pp, ga, be, out);
}

// round 8
// speedup vs baseline: 1.0351x; 1.0351x over previous
#include <cuda_runtime.h>
#include <cuda_fp16.h>
#include <cstdint>
#include <math.h>

#define S_LEN 2048
#define D_MOD 1024
#define ROWS  4096          // B*S
#define NBH   32            // B*H
#define QSCALE 0.18033688011112042f   // 0.125 * log2(e)

// ---------------- scratch (static; no allocations) ----------
__device__ __align__(128) __half g_xh [ROWS * D_MOD];
__device__ __align__(128) __half g_Wh [3 * D_MOD * D_MOD];    // [3072][1024] K-major fp16
__device__ __align__(128) __half g_Woh[D_MOD * D_MOD];
__device__ __align__(128) __half g_Q  [NBH * S_LEN * 64];     // pre-scaled by QSCALE
__device__ __align__(128) __half g_K  [NBH * S_LEN * 64];
__device__ __align__(128) __half g_V  [NBH * S_LEN * 64];
__device__ __align__(128) __half g_Vt [NBH * 64 * S_LEN];     // [bh][dk][s]
__device__ __align__(128) __half g_ctxh[ROWS * D_MOD];
__device__ __align__(128) float  g_prj[ROWS * D_MOD];

// ---------------- helpers ----------------
__device__ __forceinline__ uint32_t smem_u32(const void* p) {
    uint32_t a;
    asm("{ .reg .u64 t; cvta.to.shared.u64 t, %1; cvt.u32.u64 %0, t; }" : "=r"(a) : "l"(p));
    return a;
}
__device__ __forceinline__ void cp16(uint32_t dst, const void* src) {
    asm volatile("cp.async.cg.shared.global [%0], [%1], 16;" :: "r"(dst), "l"(src) : "memory");
}
#define CP_COMMIT() asm volatile("cp.async.commit_group;" ::: "memory")
#define CP_WAIT0()  asm volatile("cp.async.wait_group 0;" ::: "memory")
#define CP_WAIT1()  asm volatile("cp.async.wait_group 1;" ::: "memory")

__device__ __forceinline__ float ex2(float x) {
    float y;
    asm("ex2.approx.f32 %0, %1;" : "=f"(y) : "f"(x));
    return y;
}
__device__ __forceinline__ void mma16(float* d, const uint32_t* a, uint32_t b0, uint32_t b1) {
    asm volatile("mma.sync.aligned.m16n8k16.row.col.f32.f16.f16.f32 "
        "{%0,%1,%2,%3}, {%4,%5,%6,%7}, {%8,%9}, {%0,%1,%2,%3};"
        : "+f"(d[0]), "+f"(d[1]), "+f"(d[2]), "+f"(d[3])
        : "r"(a[0]), "r"(a[1]), "r"(a[2]), "r"(a[3]), "r"(b0), "r"(b1));
}
__device__ __forceinline__ void ldsm4(uint32_t& r0, uint32_t& r1, uint32_t& r2, uint32_t& r3,
                                      uint32_t addr) {
    asm volatile("ldmatrix.sync.aligned.m8n8.x4.shared.b16 {%0,%1,%2,%3}, [%4];"
        : "=r"(r0), "=r"(r1), "=r"(r2), "=r"(r3) : "r"(addr));
}

// ======================= fp16 mma.sync GEMM =======================
// C[4096, N] = A[4096,1024] @ W[N,1024]^T + bias.  BM=BN=128, BK=32 halves.
#define GPAD 20

template <int QKV>
__global__ __launch_bounds__(256, 2) void gemm_h(
    const __half* __restrict__ A, const __half* __restrict__ W,
    const float* __restrict__ b0, const float* __restrict__ b1, const float* __restrict__ b2,
    __half* __restrict__ hq, __half* __restrict__ hk, __half* __restrict__ hv,
    float* __restrict__ of)
{
    __shared__ uint32_t As[2][128 * GPAD];
    __shared__ uint32_t Bs[2][128 * GPAD];

    const int tid = threadIdx.x;
    const int wid = tid >> 5, lane = tid & 31;
    const int g = lane >> 2, t = lane & 3;
    const int wm = wid & 1, wn = wid >> 1;       // warp 64 (M) x 32 (N)
    const int m0 = blockIdx.y * 128;
    const int n0 = blockIdx.x * 128;

    const int lrow  = (lane & 7) + ((lane >> 3) & 1) * 8;
    const int lcol4 = (lane >> 4) * 4;

    const uint32_t sA[2] = {smem_u32(As[0]), smem_u32(As[1])};
    const uint32_t sB[2] = {smem_u32(Bs[0]), smem_u32(Bs[1])};

    float acc[4][4][4];
#pragma unroll
    for (int i = 0; i < 4; i++)
#pragma unroll
        for (int j = 0; j < 4; j++)
#pragma unroll
            for (int r = 0; r < 4; r++) acc[i][j][r] = 0.f;

#define G_LOAD(st, kt) do {                                                       \
    _Pragma("unroll")                                                             \
    for (int i = 0; i < 2; i++) {                                                 \
        int j = tid + i * 256;                                                    \
        int r = j >> 2, cq = j & 3;                                               \
        cp16(sA[st] + (uint32_t)(r * GPAD + cq * 4) * 4,                          \
             A + (size_t)(m0 + r) * 1024 + (kt) * 32 + cq * 8);                   \
        cp16(sB[st] + (uint32_t)(r * GPAD + cq * 4) * 4,                          \
             W + (size_t)(n0 + r) * 1024 + (kt) * 32 + cq * 8);                   \
    }                                                                             \
    CP_COMMIT();                                                                  \
} while (0)

    G_LOAD(0, 0);
    for (int kt = 0; kt < 32; kt++) {
        const int st = kt & 1;
        if (kt < 31) { G_LOAD(st ^ 1, kt + 1); CP_WAIT1(); }
        else         { CP_WAIT0(); }
        __syncthreads();

#pragma unroll
        for (int ks = 0; ks < 2; ks++) {
            uint32_t af[4][4];
#pragma unroll
            for (int mt = 0; mt < 4; mt++)
                ldsm4(af[mt][0], af[mt][1], af[mt][2], af[mt][3],
                      sA[st] + 4u * ((wm * 64 + mt * 16 + lrow) * GPAD + ks * 8 + lcol4));
#pragma unroll
            for (int np = 0; np < 2; np++) {
                uint32_t r0, r1, r2, r3;
                ldsm4(r0, r1, r2, r3,
                      sB[st] + 4u * ((wn * 32 + np * 16 + lrow) * GPAD + ks * 8 + lcol4));
#pragma unroll
                for (int mt = 0; mt < 4; mt++) {
                    mma16(acc[mt][2 * np],     af[mt], r0, r2);
                    mma16(acc[mt][2 * np + 1], af[mt], r1, r3);
                }
            }
        }
        __syncthreads();
    }

    // epilogue
#pragma unroll
    for (int mt = 0; mt < 4; mt++) {
        const int r0 = m0 + wm * 64 + mt * 16 + g;
#pragma unroll
        for (int nt = 0; nt < 4; nt++) {
            const int col = n0 + wn * 32 + nt * 8 + 2 * t;
            if (QKV) {
                const int mat = col >> 10, nl = col & 1023;
                const float* bias = (mat == 0 ? b0 : mat == 1 ? b1 : b2);
                __half* op = (mat == 0 ? hq : mat == 1 ? hk : hv);
                const int h = nl >> 6, d = nl & 63;
                const float2 bv = *(const float2*)(bias + nl);
                const int b = r0 >> 11, s = r0 & 2047;
                __half* p = op + ((size_t)((b * 16 + h) * 2048 + s)) * 64 + d;
                float v0 = acc[mt][nt][0] + bv.x, v1 = acc[mt][nt][1] + bv.y;
                float v2 = acc[mt][nt][2] + bv.x, v3 = acc[mt][nt][3] + bv.y;
                if (mat == 0) { v0 *= QSCALE; v1 *= QSCALE; v2 *= QSCALE; v3 *= QSCALE; }
                *(__half2*)p = __floats2half2_rn(v0, v1);
                *(__half2*)(p + 8 * 64) = __floats2half2_rn(v2, v3);
            } else {
                const float2 bv = *(const float2*)(b0 + col);
                float* p = of + (size_t)r0 * 1024 + col;
                *(float2*)p = make_float2(acc[mt][nt][0] + bv.x, acc[mt][nt][1] + bv.y);
                *(float2*)(p + 8 * 1024) = make_float2(acc[mt][nt][2] + bv.x,
                                                       acc[mt][nt][3] + bv.y);
            }
        }
    }
}

// ======================= fp16 flash attention =======================
// CTA: 128 queries, 8 warps (16 q-rows each). KV tiles of 64 keys.
// Q is pre-scaled by 0.125*log2(e) -> scores are in exp2 domain.
#define AP   36
#define QU   (128 * AP)
#define KVU  (64 * AP)
#define ATTN_SMEM ((QU + 4 * KVU) * 4)   // 55296 bytes

__global__ __launch_bounds__(256, 2) void attn_h(
    const __half* __restrict__ Q, const __half* __restrict__ K,
    const __half* __restrict__ Vt, __half* __restrict__ Ctx)
{
    extern __shared__ uint32_t smu[];
    uint32_t* Qs = smu;
    uint32_t* Ks = smu + QU;
    uint32_t* Vs = smu + QU + 2 * KVU;

    const int bh = blockIdx.y;
    const int q0 = blockIdx.x * 128;
    const int tid = threadIdx.x;
    const int wid = tid >> 5, lane = tid & 31;
    const int g = lane >> 2, t = lane & 3;
    const int lrow  = (lane & 7) + ((lane >> 3) & 1) * 8;
    const int lcol4 = (lane >> 4) * 4;

    const __half* Qb = Q  + (size_t)bh * S_LEN * 64;
    const __half* Kb = K  + (size_t)bh * S_LEN * 64;
    const __half* Vb = Vt + (size_t)bh * 64 * S_LEN;

    const uint32_t uQ = smem_u32(Qs);
    const uint32_t uK[2] = {smem_u32(Ks), smem_u32(Ks + KVU)};
    const uint32_t uV[2] = {smem_u32(Vs), smem_u32(Vs + KVU)};

#define LOAD_K(st, kt) do { _Pragma("unroll") for (int i = 0; i < 2; i++) { \
    int j = tid + i * 256; int r = j >> 3, cq = j & 7;                      \
    cp16(uK[st] + (uint32_t)(r * AP + cq * 4) * 4,                          \
         Kb + (size_t)((kt) * 64 + r) * 64 + cq * 8); } } while (0)
#define LOAD_V(st, kt) do { _Pragma("unroll") for (int i = 0; i < 2; i++) { \
    int j = tid + i * 256; int r = j >> 3, cq = j & 7;                      \
    cp16(uV[st] + (uint32_t)(r * AP + cq * 4) * 4,                          \
         Vb + (size_t)r * S_LEN + (kt) * 64 + cq * 8); } } while (0)

    // prologue: Q + K0 + V0
#pragma unroll
    for (int i = 0; i < 4; i++) {
        int j = tid + i * 256; int r = j >> 3, cq = j & 7;
        cp16(uQ + (uint32_t)(r * AP + cq * 4) * 4, Qb + (size_t)(q0 + r) * 64 + cq * 8);
    }
    LOAD_K(0, 0); LOAD_V(0, 0); CP_COMMIT();
    CP_WAIT0();
    __syncthreads();

    const int rbase = wid * 16 + g;

    // hoist Q fragments (dk=64 -> 4 k16 steps)
    uint32_t qf[4][4];
#pragma unroll
    for (int ks = 0; ks < 4; ks++)
        ldsm4(qf[ks][0], qf[ks][1], qf[ks][2], qf[ks][3],
              uQ + 4u * ((wid * 16 + lrow) * AP + ks * 8 + lcol4));
    __syncthreads();
    uint32_t* Ps = Qs;                        // Q smem dead; reuse as P buffer
    const uint32_t uP = uQ;

    float m0 = -1e30f, m1 = -1e30f, l0 = 0.f, l1 = 0.f;
    float oacc[8][4];
#pragma unroll
    for (int i = 0; i < 8; i++)
#pragma unroll
        for (int r = 0; r < 4; r++) oacc[i][r] = 0.f;

    for (int kt = 0; kt < 32; kt++) {
        const int st = kt & 1;
        if (kt > 0) { CP_WAIT0(); __syncthreads(); }
        if (kt < 31) { LOAD_K(st ^ 1, kt + 1); LOAD_V(st ^ 1, kt + 1); CP_COMMIT(); }

        // ---- S = Q @ K^T (already exp2-domain: Q pre-scaled) ----
        float sacc[8][4];
#pragma unroll
        for (int i = 0; i < 8; i++)
#pragma unroll
            for (int r = 0; r < 4; r++) sacc[i][r] = 0.f;

#pragma unroll
        for (int ks = 0; ks < 4; ks++) {
#pragma unroll
            for (int np = 0; np < 4; np++) {
                uint32_t r0, r1, r2, r3;
                ldsm4(r0, r1, r2, r3,
                      uK[st] + 4u * ((np * 16 + lrow) * AP + ks * 8 + lcol4));
                mma16(sacc[2 * np],     qf[ks], r0, r2);
                mma16(sacc[2 * np + 1], qf[ks], r1, r3);
            }
        }

        // ---- online softmax in exp2 domain (rows rbase, rbase+8) ----
        float rmax0 = -1e30f, rmax1 = -1e30f;
#pragma unroll
        for (int nt = 0; nt < 8; nt++) {
            rmax0 = fmaxf(rmax0, fmaxf(sacc[nt][0], sacc[nt][1]));
            rmax1 = fmaxf(rmax1, fmaxf(sacc[nt][2], sacc[nt][3]));
        }
        rmax0 = fmaxf(rmax0, __shfl_xor_sync(0xffffffffu, rmax0, 1));
        rmax0 = fmaxf(rmax0, __shfl_xor_sync(0xffffffffu, rmax0, 2));
        rmax1 = fmaxf(rmax1, __shfl_xor_sync(0xffffffffu, rmax1, 1));
        rmax1 = fmaxf(rmax1, __shfl_xor_sync(0xffffffffu, rmax1, 2));

        const float mn0 = fmaxf(m0, rmax0), mn1 = fmaxf(m1, rmax1);
        const float f0 = ex2(m0 - mn0), f1 = ex2(m1 - mn1);
        m0 = mn0; m1 = mn1;

        float rs0 = 0.f, rs1 = 0.f;
#pragma unroll
        for (int nt = 0; nt < 8; nt++) {
            const float p00 = ex2(sacc[nt][0] - m0);
            const float p01 = ex2(sacc[nt][1] - m0);
            const float p10 = ex2(sacc[nt][2] - m1);
            const float p11 = ex2(sacc[nt][3] - m1);
            rs0 += p00 + p01; rs1 += p10 + p11;
            *(__half2*)&Ps[rbase * AP + nt * 4 + t]       = __floats2half2_rn(p00, p01);
            *(__half2*)&Ps[(rbase + 8) * AP + nt * 4 + t] = __floats2half2_rn(p10, p11);
        }
        rs0 += __shfl_xor_sync(0xffffffffu, rs0, 1);
        rs0 += __shfl_xor_sync(0xffffffffu, rs0, 2);
        rs1 += __shfl_xor_sync(0xffffffffu, rs1, 1);
        rs1 += __shfl_xor_sync(0xffffffffu, rs1, 2);
        l0 = l0 * f0 + rs0; l1 = l1 * f1 + rs1;

#pragma unroll
        for (int nt = 0; nt < 8; nt++) {
            oacc[nt][0] *= f0; oacc[nt][1] *= f0;
            oacc[nt][2] *= f1; oacc[nt][3] *= f1;
        }
        __syncwarp();   // Ps rows are per-warp private

        // ---- O += P @ V  (V^T tile: [dk][key]) ----
#pragma unroll
        for (int ks = 0; ks < 4; ks++) {
            uint32_t af[4];
            ldsm4(af[0], af[1], af[2], af[3],
                  uP + 4u * ((wid * 16 + lrow) * AP + ks * 8 + lcol4));
#pragma unroll
            for (int np = 0; np < 4; np++) {
                uint32_t r0, r1, r2, r3;
                ldsm4(r0, r1, r2, r3,
                      uV[st] + 4u * ((np * 16 + lrow) * AP + ks * 8 + lcol4));
                mma16(oacc[2 * np],     af, r0, r2);
                mma16(oacc[2 * np + 1], af, r1, r3);
            }
        }
        __syncwarp();
    }

    // ---- epilogue ----
    const float inv0 = 1.f / l0, inv1 = 1.f / l1;
    const int b = bh >> 4, h = bh & 15;
    const int row0 = q0 + rbase;
    __half* base0 = Ctx + ((size_t)(b * 2048 + row0)) * 1024 + h * 64;
#pragma unroll
    for (int nt = 0; nt < 8; nt++) {
        const int col = nt * 8 + 2 * t;
        *(__half2*)(base0 + col) = __floats2half2_rn(oacc[nt][0] * inv0, oacc[nt][1] * inv0);
        *(__half2*)(base0 + 8 * 1024 + col) = __floats2half2_rn(oacc[nt][2] * inv1,
                                                                oacc[nt][3] * inv1);
    }
}

// ======================= fused prep: weights transpose + x convert ========
__global__ __launch_bounds__(256) void prep_all(
    const float* __restrict__ Wq, const float* __restrict__ Wk,
    const float* __restrict__ Wv, const float* __restrict__ Wo,
    const float* __restrict__ x,
    __half* __restrict__ Wh, __half* __restrict__ Woh, __half* __restrict__ xh)
{
    const int z = blockIdx.z;
    const int tx = threadIdx.x, ty = threadIdx.y;   // 32 x 8
    if (z == 4) {
        // convert x: 1024 blocks x 256 threads x 4 float4
        const int tl = (blockIdx.y * 32 + blockIdx.x) * 256 + ty * 32 + tx;   // 0..262143
#pragma unroll
        for (int k = 0; k < 4; k++) {
            const int i = tl + k * 262144;
            float4 v = ((const float4*)x)[i];
            ((__half2*)xh)[2 * i]     = __floats2half2_rn(v.x, v.y);
            ((__half2*)xh)[2 * i + 1] = __floats2half2_rn(v.z, v.w);
        }
        return;
    }
    __shared__ float tb[32][33];
    const float* src = (z == 0) ? Wq : (z == 1) ? Wk : (z == 2) ? Wv : Wo;
    __half* dst = (z < 3) ? (Wh + (size_t)z * D_MOD * D_MOD) : Woh;
    const int k0 = blockIdx.x * 32, n0 = blockIdx.y * 32;
#pragma unroll
    for (int i = 0; i < 4; i++)
        tb[ty + i * 8][tx] = src[(size_t)(k0 + ty + i * 8) * D_MOD + n0 + tx];
    __syncthreads();
#pragma unroll
    for (int i = 0; i < 4; i++)
        dst[(size_t)(n0 + ty + i * 8) * D_MOD + k0 + tx] = __float2half_rn(tb[tx][ty + i * 8]);
}

// V [bh][s][64] -> Vt [bh][64][s], fp16
__global__ __launch_bounds__(256) void transpose_v(const __half* __restrict__ V,
                                                   __half* __restrict__ Vt) {
    __shared__ __half tb[32][36];
    const int bh = blockIdx.z;
    const int s0 = blockIdx.x * 32, d0 = blockIdx.y * 32;
    const int tx = threadIdx.x, ty = threadIdx.y;   // 32 x 8
    const __half* src = V + (size_t)bh * S_LEN * 64;
    __half* dst = Vt + (size_t)bh * 64 * S_LEN;
#pragma unroll
    for (int i = 0; i < 4; i++)
        tb[ty + i * 8][tx] = src[(size_t)(s0 + ty + i * 8) * 64 + d0 + tx];
    __syncthreads();
#pragma unroll
    for (int i = 0; i < 4; i++)
        dst[(size_t)(d0 + ty + i * 8) * S_LEN + s0 + tx] = tb[tx][ty + i * 8];
}

// ---------------- residual + LayerNorm ------------------------------------
__global__ __launch_bounds__(256) void ln_kernel(
    const float* __restrict__ x, const float* __restrict__ prj,
    const float* __restrict__ gamma, const float* __restrict__ beta,
    float* __restrict__ out)
{
    const int row = blockIdx.x;
    const int tid = threadIdx.x;

    const float4 xv = ((const float4*)(x   + (size_t)row * D_MOD))[tid];
    const float4 pv = ((const float4*)(prj + (size_t)row * D_MOD))[tid];
    float4 h;
    h.x = xv.x + pv.x; h.y = xv.y + pv.y; h.z = xv.z + pv.z; h.w = xv.w + pv.w;

    float sum = h.x + h.y + h.z + h.w;
    float ssq = h.x * h.x + h.y * h.y + h.z * h.z + h.w * h.w;
#pragma unroll
    for (int o = 16; o > 0; o >>= 1) {
        sum += __shfl_xor_sync(0xffffffffu, sum, o);
        ssq += __shfl_xor_sync(0xffffffffu, ssq, o);
    }
    __shared__ float rs[8], rq[8];
    const int warp = tid >> 5, lane = tid & 31;
    if (lane == 0) { rs[warp] = sum; rq[warp] = ssq; }
    __syncthreads();
    float ts = 0.f, tq = 0.f;
#pragma unroll
    for (int i = 0; i < 8; i++) { ts += rs[i]; tq += rq[i]; }

    const float mu   = ts * (1.f / (float)D_MOD);
    const float var  = tq * (1.f / (float)D_MOD) - mu * mu;
    const float rstd = rsqrtf(var + 1e-5f);

    const float4 gg = ((const float4*)gamma)[tid];
    const float4 bb = ((const float4*)beta)[tid];
    float4 o;
    o.x = (h.x - mu) * rstd * gg.x + bb.x;
    o.y = (h.y - mu) * rstd * gg.y + bb.y;
    o.z = (h.z - mu) * rstd * gg.z + bb.z;
    o.w = (h.w - mu) * rstd * gg.w + bb.w;
    ((float4*)(out + (size_t)row * D_MOD))[tid] = o;
}

// ---------------- launch ----------------------------------------------------
extern "C" void kernel_launch(void* const* d_in, const int* in_sizes, int n_in,
                              void* d_out, int out_size)
{
    const float* x  = (const float*)d_in[0];
    const float* Wq = (const float*)d_in[1];
    const float* bq = (const float*)d_in[2];
    const float* Wk = (const float*)d_in[3];
    const float* bk = (const float*)d_in[4];
    const float* Wv = (const float*)d_in[5];
    const float* bv = (const float*)d_in[6];
    const float* Wo = (const float*)d_in[7];
    const float* bo = (const float*)d_in[8];
    const float* ga = (const float*)d_in[9];
    const float* be = (const float*)d_in[10];
    float* out = (float*)d_out;

    __half *Xh, *Wh, *Woh, *Qp, *Kp, *Vp, *Vtp, *Ch;
    float *Pp;
    cudaGetSymbolAddress((void**)&Xh,  g_xh);
    cudaGetSymbolAddress((void**)&Wh,  g_Wh);
    cudaGetSymbolAddress((void**)&Woh, g_Woh);
    cudaGetSymbolAddress((void**)&Qp,  g_Q);
    cudaGetSymbolAddress((void**)&Kp,  g_K);
    cudaGetSymbolAddress((void**)&Vp,  g_V);
    cudaGetSymbolAddress((void**)&Vtp, g_Vt);
    cudaGetSymbolAddress((void**)&Ch,  g_ctxh);
    cudaGetSymbolAddress((void**)&Pp,  g_prj);

    cudaFuncSetAttribute(attn_h, cudaFuncAttributeMaxDynamicSharedMemorySize, ATTN_SMEM);

    prep_all<<<dim3(32, 32, 5), dim3(32, 8)>>>(Wq, Wk, Wv, Wo, x, Wh, Woh, Xh);

    gemm_h<1><<<dim3(24, 32), 256>>>(Xh, Wh, bq, bk, bv, Qp, Kp, Vp, nullptr);

    transpose_v<<<dim3(64, 2, NBH), dim3(32, 8)>>>(Vp, Vtp);

    attn_h<<<dim3(S_LEN / 128, NBH), 256, ATTN_SMEM>>>(Qp, Kp, Vtp, Ch);

    gemm_h<0><<<dim3(8, 32), 256>>>(Ch, Woh, bo, bo, bo, nullptr, nullptr, nullptr, Pp);

    ln_kernel<<<ROWS, 256>>>(x, Pp, ga, be, out);
}

// round 9
// speedup vs baseline: 1.0743x; 1.0379x over previous
#include <cuda_runtime.h>
#include <cuda_fp16.h>
#include <cstdint>
#include <math.h>

#define S_LEN 2048
#define D_MOD 1024
#define ROWS  4096          // B*S
#define NBH   32            // B*H
#define QSCALE 0.18033688011112042f   // 0.125 * log2(e)
#define POFF   8.0f                   // fixed exp2-domain offset (cancels in O/l)

// ---------------- scratch (static; no allocations) ----------
__device__ __align__(128) __half g_xh [ROWS * D_MOD];
__device__ __align__(128) __half g_Wh [3 * D_MOD * D_MOD];    // [3072][1024] K-major fp16
__device__ __align__(128) __half g_Woh[D_MOD * D_MOD];
__device__ __align__(128) __half g_Q  [NBH * S_LEN * 64];     // pre-scaled by QSCALE
__device__ __align__(128) __half g_K  [NBH * S_LEN * 64];
__device__ __align__(128) __half g_V  [NBH * S_LEN * 64];
__device__ __align__(128) __half g_Vt [NBH * 64 * S_LEN];     // [bh][dk][s]
__device__ __align__(128) __half g_ctxh[ROWS * D_MOD];
__device__ __align__(128) float  g_prj[ROWS * D_MOD];

// ---------------- helpers ----------------
__device__ __forceinline__ uint32_t smem_u32(const void* p) {
    uint32_t a;
    asm("{ .reg .u64 t; cvta.to.shared.u64 t, %1; cvt.u32.u64 %0, t; }" : "=r"(a) : "l"(p));
    return a;
}
__device__ __forceinline__ void cp16(uint32_t dst, const void* src) {
    asm volatile("cp.async.cg.shared.global [%0], [%1], 16;" :: "r"(dst), "l"(src) : "memory");
}
#define CP_COMMIT() asm volatile("cp.async.commit_group;" ::: "memory")
#define CP_WAIT0()  asm volatile("cp.async.wait_group 0;" ::: "memory")
#define CP_WAIT1()  asm volatile("cp.async.wait_group 1;" ::: "memory")

__device__ __forceinline__ float ex2(float x) {
    float y;
    asm("ex2.approx.f32 %0, %1;" : "=f"(y) : "f"(x));
    return y;
}
__device__ __forceinline__ void mma16(float* d, const uint32_t* a, uint32_t b0, uint32_t b1) {
    asm volatile("mma.sync.aligned.m16n8k16.row.col.f32.f16.f16.f32 "
        "{%0,%1,%2,%3}, {%4,%5,%6,%7}, {%8,%9}, {%0,%1,%2,%3};"
        : "+f"(d[0]), "+f"(d[1]), "+f"(d[2]), "+f"(d[3])
        : "r"(a[0]), "r"(a[1]), "r"(a[2]), "r"(a[3]), "r"(b0), "r"(b1));
}
__device__ __forceinline__ void ldsm4(uint32_t& r0, uint32_t& r1, uint32_t& r2, uint32_t& r3,
                                      uint32_t addr) {
    asm volatile("ldmatrix.sync.aligned.m8n8.x4.shared.b16 {%0,%1,%2,%3}, [%4];"
        : "=r"(r0), "=r"(r1), "=r"(r2), "=r"(r3) : "r"(addr));
}

// ======================= fp16 mma.sync GEMM =======================
// C[4096, N] = A[4096,1024] @ W[N,1024]^T + bias.  BM=BN=128, BK=32 halves.
#define GPAD 20

template <int QKV>
__global__ __launch_bounds__(256, 2) void gemm_h(
    const __half* __restrict__ A, const __half* __restrict__ W,
    const float* __restrict__ b0, const float* __restrict__ b1, const float* __restrict__ b2,
    __half* __restrict__ hq, __half* __restrict__ hk, __half* __restrict__ hv,
    float* __restrict__ of)
{
    __shared__ uint32_t As[2][128 * GPAD];
    __shared__ uint32_t Bs[2][128 * GPAD];

    const int tid = threadIdx.x;
    const int wid = tid >> 5, lane = tid & 31;
    const int g = lane >> 2, t = lane & 3;
    const int wm = wid & 1, wn = wid >> 1;       // warp 64 (M) x 32 (N)
    const int m0 = blockIdx.y * 128;
    const int n0 = blockIdx.x * 128;

    const int lrow  = (lane & 7) + ((lane >> 3) & 1) * 8;
    const int lcol4 = (lane >> 4) * 4;

    const uint32_t sA[2] = {smem_u32(As[0]), smem_u32(As[1])};
    const uint32_t sB[2] = {smem_u32(Bs[0]), smem_u32(Bs[1])};

    float acc[4][4][4];
#pragma unroll
    for (int i = 0; i < 4; i++)
#pragma unroll
        for (int j = 0; j < 4; j++)
#pragma unroll
            for (int r = 0; r < 4; r++) acc[i][j][r] = 0.f;

#define G_LOAD(st, kt) do {                                                       \
    _Pragma("unroll")                                                             \
    for (int i = 0; i < 2; i++) {                                                 \
        int j = tid + i * 256;                                                    \
        int r = j >> 2, cq = j & 3;                                               \
        cp16(sA[st] + (uint32_t)(r * GPAD + cq * 4) * 4,                          \
             A + (size_t)(m0 + r) * 1024 + (kt) * 32 + cq * 8);                   \
        cp16(sB[st] + (uint32_t)(r * GPAD + cq * 4) * 4,                          \
             W + (size_t)(n0 + r) * 1024 + (kt) * 32 + cq * 8);                   \
    }                                                                             \
    CP_COMMIT();                                                                  \
} while (0)

    G_LOAD(0, 0);
    for (int kt = 0; kt < 32; kt++) {
        const int st = kt & 1;
        if (kt < 31) { G_LOAD(st ^ 1, kt + 1); CP_WAIT1(); }
        else         { CP_WAIT0(); }
        __syncthreads();

#pragma unroll
        for (int ks = 0; ks < 2; ks++) {
            uint32_t af[4][4];
#pragma unroll
            for (int mt = 0; mt < 4; mt++)
                ldsm4(af[mt][0], af[mt][1], af[mt][2], af[mt][3],
                      sA[st] + 4u * ((wm * 64 + mt * 16 + lrow) * GPAD + ks * 8 + lcol4));
#pragma unroll
            for (int np = 0; np < 2; np++) {
                uint32_t r0, r1, r2, r3;
                ldsm4(r0, r1, r2, r3,
                      sB[st] + 4u * ((wn * 32 + np * 16 + lrow) * GPAD + ks * 8 + lcol4));
#pragma unroll
                for (int mt = 0; mt < 4; mt++) {
                    mma16(acc[mt][2 * np],     af[mt], r0, r2);
                    mma16(acc[mt][2 * np + 1], af[mt], r1, r3);
                }
            }
        }
        __syncthreads();
    }

    // epilogue
#pragma unroll
    for (int mt = 0; mt < 4; mt++) {
        const int r0 = m0 + wm * 64 + mt * 16 + g;
#pragma unroll
        for (int nt = 0; nt < 4; nt++) {
            const int col = n0 + wn * 32 + nt * 8 + 2 * t;
            if (QKV) {
                const int mat = col >> 10, nl = col & 1023;
                const float* bias = (mat == 0 ? b0 : mat == 1 ? b1 : b2);
                __half* op = (mat == 0 ? hq : mat == 1 ? hk : hv);
                const int h = nl >> 6, d = nl & 63;
                const float2 bv = *(const float2*)(bias + nl);
                const int b = r0 >> 11, s = r0 & 2047;
                __half* p = op + ((size_t)((b * 16 + h) * 2048 + s)) * 64 + d;
                float v0 = acc[mt][nt][0] + bv.x, v1 = acc[mt][nt][1] + bv.y;
                float v2 = acc[mt][nt][2] + bv.x, v3 = acc[mt][nt][3] + bv.y;
                if (mat == 0) { v0 *= QSCALE; v1 *= QSCALE; v2 *= QSCALE; v3 *= QSCALE; }
                *(__half2*)p = __floats2half2_rn(v0, v1);
                *(__half2*)(p + 8 * 64) = __floats2half2_rn(v2, v3);
            } else {
                const float2 bv = *(const float2*)(b0 + col);
                float* p = of + (size_t)r0 * 1024 + col;
                *(float2*)p = make_float2(acc[mt][nt][0] + bv.x, acc[mt][nt][1] + bv.y);
                *(float2*)(p + 8 * 1024) = make_float2(acc[mt][nt][2] + bv.x,
                                                       acc[mt][nt][3] + bv.y);
            }
        }
    }
}

// ======================= fp16 flash attention (fixed-offset softmax) ======
// CTA: 128 queries, 8 warps (16 q-rows each). KV tiles of 64 keys.
// Q pre-scaled by 0.125*log2(e); p = exp2(s - POFF); O = (P@V)/l, offset cancels.
#define AP   36
#define QU   (128 * AP)
#define KVU  (64 * AP)
#define ATTN_SMEM ((QU + 4 * KVU) * 4)   // 55296 bytes

__global__ __launch_bounds__(256, 2) void attn_h(
    const __half* __restrict__ Q, const __half* __restrict__ K,
    const __half* __restrict__ Vt, __half* __restrict__ Ctx)
{
    extern __shared__ uint32_t smu[];
    uint32_t* Qs = smu;
    uint32_t* Ks = smu + QU;
    uint32_t* Vs = smu + QU + 2 * KVU;

    const int bh = blockIdx.y;
    const int q0 = blockIdx.x * 128;
    const int tid = threadIdx.x;
    const int wid = tid >> 5, lane = tid & 31;
    const int g = lane >> 2, t = lane & 3;
    const int lrow  = (lane & 7) + ((lane >> 3) & 1) * 8;
    const int lcol4 = (lane >> 4) * 4;

    const __half* Qb = Q  + (size_t)bh * S_LEN * 64;
    const __half* Kb = K  + (size_t)bh * S_LEN * 64;
    const __half* Vb = Vt + (size_t)bh * 64 * S_LEN;

    const uint32_t uQ = smem_u32(Qs);
    const uint32_t uK[2] = {smem_u32(Ks), smem_u32(Ks + KVU)};
    const uint32_t uV[2] = {smem_u32(Vs), smem_u32(Vs + KVU)};

#define LOAD_K(st, kt) do { _Pragma("unroll") for (int i = 0; i < 2; i++) { \
    int j = tid + i * 256; int r = j >> 3, cq = j & 7;                      \
    cp16(uK[st] + (uint32_t)(r * AP + cq * 4) * 4,                          \
         Kb + (size_t)((kt) * 64 + r) * 64 + cq * 8); } } while (0)
#define LOAD_V(st, kt) do { _Pragma("unroll") for (int i = 0; i < 2; i++) { \
    int j = tid + i * 256; int r = j >> 3, cq = j & 7;                      \
    cp16(uV[st] + (uint32_t)(r * AP + cq * 4) * 4,                          \
         Vb + (size_t)r * S_LEN + (kt) * 64 + cq * 8); } } while (0)

    // prologue: Q + K0 + V0
#pragma unroll
    for (int i = 0; i < 4; i++) {
        int j = tid + i * 256; int r = j >> 3, cq = j & 7;
        cp16(uQ + (uint32_t)(r * AP + cq * 4) * 4, Qb + (size_t)(q0 + r) * 64 + cq * 8);
    }
    LOAD_K(0, 0); LOAD_V(0, 0); CP_COMMIT();
    CP_WAIT0();
    __syncthreads();

    const int rbase = wid * 16 + g;

    // hoist Q fragments (dk=64 -> 4 k16 steps)
    uint32_t qf[4][4];
#pragma unroll
    for (int ks = 0; ks < 4; ks++)
        ldsm4(qf[ks][0], qf[ks][1], qf[ks][2], qf[ks][3],
              uQ + 4u * ((wid * 16 + lrow) * AP + ks * 8 + lcol4));
    __syncthreads();
    uint32_t* Ps = Qs;                        // Q smem dead; reuse as P buffer
    const uint32_t uP = uQ;

    float l0 = 0.f, l1 = 0.f;
    float oacc[8][4];
#pragma unroll
    for (int i = 0; i < 8; i++)
#pragma unroll
        for (int r = 0; r < 4; r++) oacc[i][r] = 0.f;

    for (int kt = 0; kt < 32; kt++) {
        const int st = kt & 1;
        if (kt > 0) { CP_WAIT0(); __syncthreads(); }
        if (kt < 31) { LOAD_K(st ^ 1, kt + 1); LOAD_V(st ^ 1, kt + 1); CP_COMMIT(); }

        // ---- S = Q @ K^T (exp2-domain scores) ----
        float sacc[8][4];
#pragma unroll
        for (int i = 0; i < 8; i++)
#pragma unroll
            for (int r = 0; r < 4; r++) sacc[i][r] = 0.f;

#pragma unroll
        for (int ks = 0; ks < 4; ks++) {
#pragma unroll
            for (int np = 0; np < 4; np++) {
                uint32_t r0, r1, r2, r3;
                ldsm4(r0, r1, r2, r3,
                      uK[st] + 4u * ((np * 16 + lrow) * AP + ks * 8 + lcol4));
                mma16(sacc[2 * np],     qf[ks], r0, r2);
                mma16(sacc[2 * np + 1], qf[ks], r1, r3);
            }
        }

        // ---- fixed-offset softmax: p = exp2(s - POFF); no max, no rescale ----
        float rs0 = 0.f, rs1 = 0.f;
#pragma unroll
        for (int nt = 0; nt < 8; nt++) {
            const float p00 = ex2(sacc[nt][0] - POFF);
            const float p01 = ex2(sacc[nt][1] - POFF);
            const float p10 = ex2(sacc[nt][2] - POFF);
            const float p11 = ex2(sacc[nt][3] - POFF);
            rs0 += p00 + p01; rs1 += p10 + p11;
            *(__half2*)&Ps[rbase * AP + nt * 4 + t]       = __floats2half2_rn(p00, p01);
            *(__half2*)&Ps[(rbase + 8) * AP + nt * 4 + t] = __floats2half2_rn(p10, p11);
        }
        rs0 += __shfl_xor_sync(0xffffffffu, rs0, 1);
        rs0 += __shfl_xor_sync(0xffffffffu, rs0, 2);
        rs1 += __shfl_xor_sync(0xffffffffu, rs1, 1);
        rs1 += __shfl_xor_sync(0xffffffffu, rs1, 2);
        l0 += rs0; l1 += rs1;

        __syncwarp();   // Ps rows are per-warp private

        // ---- O += P @ V  (V^T tile: [dk][key]) ----
#pragma unroll
        for (int ks = 0; ks < 4; ks++) {
            uint32_t af[4];
            ldsm4(af[0], af[1], af[2], af[3],
                  uP + 4u * ((wid * 16 + lrow) * AP + ks * 8 + lcol4));
#pragma unroll
            for (int np = 0; np < 4; np++) {
                uint32_t r0, r1, r2, r3;
                ldsm4(r0, r1, r2, r3,
                      uV[st] + 4u * ((np * 16 + lrow) * AP + ks * 8 + lcol4));
                mma16(oacc[2 * np],     af, r0, r2);
                mma16(oacc[2 * np + 1], af, r1, r3);
            }
        }
        __syncwarp();
    }

    // ---- epilogue ----
    const float inv0 = 1.f / l0, inv1 = 1.f / l1;
    const int b = bh >> 4, h = bh & 15;
    const int row0 = q0 + rbase;
    __half* base0 = Ctx + ((size_t)(b * 2048 + row0)) * 1024 + h * 64;
#pragma unroll
    for (int nt = 0; nt < 8; nt++) {
        const int col = nt * 8 + 2 * t;
        *(__half2*)(base0 + col) = __floats2half2_rn(oacc[nt][0] * inv0, oacc[nt][1] * inv0);
        *(__half2*)(base0 + 8 * 1024 + col) = __floats2half2_rn(oacc[nt][2] * inv1,
                                                                oacc[nt][3] * inv1);
    }
}

// ======================= fused prep: weights transpose + x convert ========
__global__ __launch_bounds__(256) void prep_all(
    const float* __restrict__ Wq, const float* __restrict__ Wk,
    const float* __restrict__ Wv, const float* __restrict__ Wo,
    const float* __restrict__ x,
    __half* __restrict__ Wh, __half* __restrict__ Woh, __half* __restrict__ xh)
{
    const int z = blockIdx.z;
    const int tx = threadIdx.x, ty = threadIdx.y;   // 32 x 8
    if (z == 4) {
        const int tl = (blockIdx.y * 32 + blockIdx.x) * 256 + ty * 32 + tx;
#pragma unroll
        for (int k = 0; k < 4; k++) {
            const int i = tl + k * 262144;
            float4 v = ((const float4*)x)[i];
            ((__half2*)xh)[2 * i]     = __floats2half2_rn(v.x, v.y);
            ((__half2*)xh)[2 * i + 1] = __floats2half2_rn(v.z, v.w);
        }
        return;
    }
    __shared__ float tb[32][33];
    const float* src = (z == 0) ? Wq : (z == 1) ? Wk : (z == 2) ? Wv : Wo;
    __half* dst = (z < 3) ? (Wh + (size_t)z * D_MOD * D_MOD) : Woh;
    const int k0 = blockIdx.x * 32, n0 = blockIdx.y * 32;
#pragma unroll
    for (int i = 0; i < 4; i++)
        tb[ty + i * 8][tx] = src[(size_t)(k0 + ty + i * 8) * D_MOD + n0 + tx];
    __syncthreads();
#pragma unroll
    for (int i = 0; i < 4; i++)
        dst[(size_t)(n0 + ty + i * 8) * D_MOD + k0 + tx] = __float2half_rn(tb[tx][ty + i * 8]);
}

// V [bh][s][64] -> Vt [bh][64][s], fp16
__global__ __launch_bounds__(256) void transpose_v(const __half* __restrict__ V,
                                                   __half* __restrict__ Vt) {
    __shared__ __half tb[32][36];
    const int bh = blockIdx.z;
    const int s0 = blockIdx.x * 32, d0 = blockIdx.y * 32;
    const int tx = threadIdx.x, ty = threadIdx.y;   // 32 x 8
    const __half* src = V + (size_t)bh * S_LEN * 64;
    __half* dst = Vt + (size_t)bh * 64 * S_LEN;
#pragma unroll
    for (int i = 0; i < 4; i++)
        tb[ty + i * 8][tx] = src[(size_t)(s0 + ty + i * 8) * 64 + d0 + tx];
    __syncthreads();
#pragma unroll
    for (int i = 0; i < 4; i++)
        dst[(size_t)(d0 + ty + i * 8) * S_LEN + s0 + tx] = tb[tx][ty + i * 8];
}

// ---------------- residual + LayerNorm ------------------------------------
__global__ __launch_bounds__(256) void ln_kernel(
    const float* __restrict__ x, const float* __restrict__ prj,
    const float* __restrict__ gamma, const float* __restrict__ beta,
    float* __restrict__ out)
{
    const int row = blockIdx.x;
    const int tid = threadIdx.x;

    const float4 xv = ((const float4*)(x   + (size_t)row * D_MOD))[tid];
    const float4 pv = ((const float4*)(prj + (size_t)row * D_MOD))[tid];
    float4 h;
    h.x = xv.x + pv.x; h.y = xv.y + pv.y; h.z = xv.z + pv.z; h.w = xv.w + pv.w;

    float sum = h.x + h.y + h.z + h.w;
    float ssq = h.x * h.x + h.y * h.y + h.z * h.z + h.w * h.w;
#pragma unroll
    for (int o = 16; o > 0; o >>= 1) {
        sum += __shfl_xor_sync(0xffffffffu, sum, o);
        ssq += __shfl_xor_sync(0xffffffffu, ssq, o);
    }
    __shared__ float rs[8], rq[8];
    const int warp = tid >> 5, lane = tid & 31;
    if (lane == 0) { rs[warp] = sum; rq[warp] = ssq; }
    __syncthreads();
    float ts = 0.f, tq = 0.f;
#pragma unroll
    for (int i = 0; i < 8; i++) { ts += rs[i]; tq += rq[i]; }

    const float mu   = ts * (1.f / (float)D_MOD);
    const float var  = tq * (1.f / (float)D_MOD) - mu * mu;
    const float rstd = rsqrtf(var + 1e-5f);

    const float4 gg = ((const float4*)gamma)[tid];
    const float4 bb = ((const float4*)beta)[tid];
    float4 o;
    o.x = (h.x - mu) * rstd * gg.x + bb.x;
    o.y = (h.y - mu) * rstd * gg.y + bb.y;
    o.z = (h.z - mu) * rstd * gg.z + bb.z;
    o.w = (h.w - mu) * rstd * gg.w + bb.w;
    ((float4*)(out + (size_t)row * D_MOD))[tid] = o;
}

// ---------------- launch ----------------------------------------------------
extern "C" void kernel_launch(void* const* d_in, const int* in_sizes, int n_in,
                              void* d_out, int out_size)
{
    const float* x  = (const float*)d_in[0];
    const float* Wq = (const float*)d_in[1];
    const float* bq = (const float*)d_in[2];
    const float* Wk = (const float*)d_in[3];
    const float* bk = (const float*)d_in[4];
    const float* Wv = (const float*)d_in[5];
    const float* bv = (const float*)d_in[6];
    const float* Wo = (const float*)d_in[7];
    const float* bo = (const float*)d_in[8];
    const float* ga = (const float*)d_in[9];
    const float* be = (const float*)d_in[10];
    float* out = (float*)d_out;

    __half *Xh, *Wh, *Woh, *Qp, *Kp, *Vp, *Vtp, *Ch;
    float *Pp;
    cudaGetSymbolAddress((void**)&Xh,  g_xh);
    cudaGetSymbolAddress((void**)&Wh,  g_Wh);
    cudaGetSymbolAddress((void**)&Woh, g_Woh);
    cudaGetSymbolAddress((void**)&Qp,  g_Q);
    cudaGetSymbolAddress((void**)&Kp,  g_K);
    cudaGetSymbolAddress((void**)&Vp,  g_V);
    cudaGetSymbolAddress((void**)&Vtp, g_Vt);
    cudaGetSymbolAddress((void**)&Ch,  g_ctxh);
    cudaGetSymbolAddress((void**)&Pp,  g_prj);

    cudaFuncSetAttribute(attn_h, cudaFuncAttributeMaxDynamicSharedMemorySize, ATTN_SMEM);

    prep_all<<<dim3(32, 32, 5), dim3(32, 8)>>>(Wq, Wk, Wv, Wo, x, Wh, Woh, Xh);

    gemm_h<1><<<dim3(24, 32), 256>>>(Xh, Wh, bq, bk, bv, Qp, Kp, Vp, nullptr);

    transpose_v<<<dim3(64, 2, NBH), dim3(32, 8)>>>(Vp, Vtp);

    attn_h<<<dim3(S_LEN / 128, NBH), 256, ATTN_SMEM>>>(Qp, Kp, Vtp, Ch);

    gemm_h<0><<<dim3(8, 32), 256>>>(Ch, Woh, bo, bo, bo, nullptr, nullptr, nullptr, Pp);

    ln_kernel<<<ROWS, 256>>>(x, Pp, ga, be, out);
}

// round 10
// speedup vs baseline: 1.1255x; 1.0476x over previous
#include <cuda_runtime.h>
#include <cuda_fp16.h>
#include <cstdint>
#include <math.h>

#define S_LEN 2048
#define D_MOD 1024
#define ROWS  4096          // B*S
#define NBH   32            // B*H
#define QSCALE 0.18033688011112042f   // 0.125 * log2(e)
#define POFF   8.0f                   // fixed exp2-domain offset (cancels in O/l)
#define ONES2  0x3C003C00u            // half2(1,1)

// ---------------- scratch (static; no allocations) ----------
__device__ __align__(128) __half g_xh [ROWS * D_MOD];
__device__ __align__(128) __half g_Wh [3 * D_MOD * D_MOD];    // [3072][1024] K-major fp16
__device__ __align__(128) __half g_Woh[D_MOD * D_MOD];
__device__ __align__(128) __half g_Q  [NBH * S_LEN * 64];     // pre-scaled by QSCALE
__device__ __align__(128) __half g_K  [NBH * S_LEN * 64];
__device__ __align__(128) __half g_V  [NBH * S_LEN * 64];
__device__ __align__(128) __half g_Vt [NBH * 64 * S_LEN];     // [bh][dk][s]
__device__ __align__(128) __half g_ctxh[ROWS * D_MOD];
__device__ __align__(128) float  g_prj[ROWS * D_MOD];

// ---------------- helpers ----------------
__device__ __forceinline__ uint32_t smem_u32(const void* p) {
    uint32_t a;
    asm("{ .reg .u64 t; cvta.to.shared.u64 t, %1; cvt.u32.u64 %0, t; }" : "=r"(a) : "l"(p));
    return a;
}
__device__ __forceinline__ void cp16(uint32_t dst, const void* src) {
    asm volatile("cp.async.cg.shared.global [%0], [%1], 16;" :: "r"(dst), "l"(src) : "memory");
}
#define CP_COMMIT() asm volatile("cp.async.commit_group;" ::: "memory")
#define CP_WAIT0()  asm volatile("cp.async.wait_group 0;" ::: "memory")
#define CP_WAIT1()  asm volatile("cp.async.wait_group 1;" ::: "memory")

// p = exp2(half2(a - POFF, b - POFF)), computed with one MUFU per pair
__device__ __forceinline__ uint32_t pexp2(float a, float b) {
    __half2 h = __floats2half2_rn(a - POFF, b - POFF);
    uint32_t u = *reinterpret_cast<uint32_t*>(&h);
    uint32_t r;
    asm("ex2.approx.f16x2 %0, %1;" : "=r"(r) : "r"(u));
    return r;
}
__device__ __forceinline__ void mma16(float* d, const uint32_t* a, uint32_t b0, uint32_t b1) {
    asm volatile("mma.sync.aligned.m16n8k16.row.col.f32.f16.f16.f32 "
        "{%0,%1,%2,%3}, {%4,%5,%6,%7}, {%8,%9}, {%0,%1,%2,%3};"
        : "+f"(d[0]), "+f"(d[1]), "+f"(d[2]), "+f"(d[3])
        : "r"(a[0]), "r"(a[1]), "r"(a[2]), "r"(a[3]), "r"(b0), "r"(b1));
}
__device__ __forceinline__ void ldsm4(uint32_t& r0, uint32_t& r1, uint32_t& r2, uint32_t& r3,
                                      uint32_t addr) {
    asm volatile("ldmatrix.sync.aligned.m8n8.x4.shared.b16 {%0,%1,%2,%3}, [%4];"
        : "=r"(r0), "=r"(r1), "=r"(r2), "=r"(r3) : "r"(addr));
}

// ======================= fp16 mma.sync GEMM =======================
// C[4096, N] = A[4096,1024] @ W[N,1024]^T + bias.  BM=BN=128, BK=32 halves.
#define GPAD 20

template <int QKV>
__global__ __launch_bounds__(256, 2) void gemm_h(
    const __half* __restrict__ A, const __half* __restrict__ W,
    const float* __restrict__ b0, const float* __restrict__ b1, const float* __restrict__ b2,
    __half* __restrict__ hq, __half* __restrict__ hk, __half* __restrict__ hv,
    float* __restrict__ of)
{
    __shared__ uint32_t As[2][128 * GPAD];
    __shared__ uint32_t Bs[2][128 * GPAD];

    const int tid = threadIdx.x;
    const int wid = tid >> 5, lane = tid & 31;
    const int g = lane >> 2, t = lane & 3;
    const int wm = wid & 1, wn = wid >> 1;       // warp 64 (M) x 32 (N)
    const int m0 = blockIdx.y * 128;
    const int n0 = blockIdx.x * 128;

    const int lrow  = (lane & 7) + ((lane >> 3) & 1) * 8;
    const int lcol4 = (lane >> 4) * 4;

    const uint32_t sA[2] = {smem_u32(As[0]), smem_u32(As[1])};
    const uint32_t sB[2] = {smem_u32(Bs[0]), smem_u32(Bs[1])};

    float acc[4][4][4];
#pragma unroll
    for (int i = 0; i < 4; i++)
#pragma unroll
        for (int j = 0; j < 4; j++)
#pragma unroll
            for (int r = 0; r < 4; r++) acc[i][j][r] = 0.f;

#define G_LOAD(st, kt) do {                                                       \
    _Pragma("unroll")                                                             \
    for (int i = 0; i < 2; i++) {                                                 \
        int j = tid + i * 256;                                                    \
        int r = j >> 2, cq = j & 3;                                               \
        cp16(sA[st] + (uint32_t)(r * GPAD + cq * 4) * 4,                          \
             A + (size_t)(m0 + r) * 1024 + (kt) * 32 + cq * 8);                   \
        cp16(sB[st] + (uint32_t)(r * GPAD + cq * 4) * 4,                          \
             W + (size_t)(n0 + r) * 1024 + (kt) * 32 + cq * 8);                   \
    }                                                                             \
    CP_COMMIT();                                                                  \
} while (0)

    G_LOAD(0, 0);
    for (int kt = 0; kt < 32; kt++) {
        const int st = kt & 1;
        if (kt < 31) { G_LOAD(st ^ 1, kt + 1); CP_WAIT1(); }
        else         { CP_WAIT0(); }
        __syncthreads();

#pragma unroll
        for (int ks = 0; ks < 2; ks++) {
            uint32_t af[4][4];
#pragma unroll
            for (int mt = 0; mt < 4; mt++)
                ldsm4(af[mt][0], af[mt][1], af[mt][2], af[mt][3],
                      sA[st] + 4u * ((wm * 64 + mt * 16 + lrow) * GPAD + ks * 8 + lcol4));
#pragma unroll
            for (int np = 0; np < 2; np++) {
                uint32_t r0, r1, r2, r3;
                ldsm4(r0, r1, r2, r3,
                      sB[st] + 4u * ((wn * 32 + np * 16 + lrow) * GPAD + ks * 8 + lcol4));
#pragma unroll
                for (int mt = 0; mt < 4; mt++) {
                    mma16(acc[mt][2 * np],     af[mt], r0, r2);
                    mma16(acc[mt][2 * np + 1], af[mt], r1, r3);
                }
            }
        }
        __syncthreads();
    }

    // epilogue
#pragma unroll
    for (int mt = 0; mt < 4; mt++) {
        const int r0 = m0 + wm * 64 + mt * 16 + g;
#pragma unroll
        for (int nt = 0; nt < 4; nt++) {
            const int col = n0 + wn * 32 + nt * 8 + 2 * t;
            if (QKV) {
                const int mat = col >> 10, nl = col & 1023;
                const float* bias = (mat == 0 ? b0 : mat == 1 ? b1 : b2);
                __half* op = (mat == 0 ? hq : mat == 1 ? hk : hv);
                const int h = nl >> 6, d = nl & 63;
                const float2 bv = *(const float2*)(bias + nl);
                const int b = r0 >> 11, s = r0 & 2047;
                __half* p = op + ((size_t)((b * 16 + h) * 2048 + s)) * 64 + d;
                float v0 = acc[mt][nt][0] + bv.x, v1 = acc[mt][nt][1] + bv.y;
                float v2 = acc[mt][nt][2] + bv.x, v3 = acc[mt][nt][3] + bv.y;
                if (mat == 0) { v0 *= QSCALE; v1 *= QSCALE; v2 *= QSCALE; v3 *= QSCALE; }
                *(__half2*)p = __floats2half2_rn(v0, v1);
                *(__half2*)(p + 8 * 64) = __floats2half2_rn(v2, v3);
            } else {
                const float2 bv = *(const float2*)(b0 + col);
                float* p = of + (size_t)r0 * 1024 + col;
                *(float2*)p = make_float2(acc[mt][nt][0] + bv.x, acc[mt][nt][1] + bv.y);
                *(float2*)(p + 8 * 1024) = make_float2(acc[mt][nt][2] + bv.x,
                                                       acc[mt][nt][3] + bv.y);
            }
        }
    }
}

// ======================= fp16 flash attention ==============================
// CTA: 128 queries, 8 warps (16 q-rows each). KV tiles of 64 keys.
// Q pre-scaled by 0.125*log2(e); p = exp2(s - POFF); offset cancels in O/l.
// P lives in registers (score C-fragment == P@V A-fragment layout);
// l computed by MMA against an all-ones B fragment.
#define AP   36
#define QU   (128 * AP)
#define KVU  (64 * AP)
#define ATTN_SMEM ((QU + 4 * KVU) * 4)   // 55296 bytes

__global__ __launch_bounds__(256, 2) void attn_h(
    const __half* __restrict__ Q, const __half* __restrict__ K,
    const __half* __restrict__ Vt, __half* __restrict__ Ctx)
{
    extern __shared__ uint32_t smu[];
    uint32_t* Qs = smu;
    uint32_t* Ks = smu + QU;
    uint32_t* Vs = smu + QU + 2 * KVU;

    const int bh = blockIdx.y;
    const int q0 = blockIdx.x * 128;
    const int tid = threadIdx.x;
    const int wid = tid >> 5, lane = tid & 31;
    const int g = lane >> 2, t = lane & 3;
    const int lrow  = (lane & 7) + ((lane >> 3) & 1) * 8;
    const int lcol4 = (lane >> 4) * 4;

    const __half* Qb = Q  + (size_t)bh * S_LEN * 64;
    const __half* Kb = K  + (size_t)bh * S_LEN * 64;
    const __half* Vb = Vt + (size_t)bh * 64 * S_LEN;

    const uint32_t uQ = smem_u32(Qs);
    const uint32_t uK[2] = {smem_u32(Ks), smem_u32(Ks + KVU)};
    const uint32_t uV[2] = {smem_u32(Vs), smem_u32(Vs + KVU)};

#define LOAD_K(st, kt) do { _Pragma("unroll") for (int i = 0; i < 2; i++) { \
    int j = tid + i * 256; int r = j >> 3, cq = j & 7;                      \
    cp16(uK[st] + (uint32_t)(r * AP + cq * 4) * 4,                          \
         Kb + (size_t)((kt) * 64 + r) * 64 + cq * 8); } } while (0)
#define LOAD_V(st, kt) do { _Pragma("unroll") for (int i = 0; i < 2; i++) { \
    int j = tid + i * 256; int r = j >> 3, cq = j & 7;                      \
    cp16(uV[st] + (uint32_t)(r * AP + cq * 4) * 4,                          \
         Vb + (size_t)r * S_LEN + (kt) * 64 + cq * 8); } } while (0)

    // prologue: Q + K0 + V0
#pragma unroll
    for (int i = 0; i < 4; i++) {
        int j = tid + i * 256; int r = j >> 3, cq = j & 7;
        cp16(uQ + (uint32_t)(r * AP + cq * 4) * 4, Qb + (size_t)(q0 + r) * 64 + cq * 8);
    }
    LOAD_K(0, 0); LOAD_V(0, 0); CP_COMMIT();
    CP_WAIT0();
    __syncthreads();

    const int rbase = wid * 16 + g;

    // hoist Q fragments (dk=64 -> 4 k16 steps)
    uint32_t qf[4][4];
#pragma unroll
    for (int ks = 0; ks < 4; ks++)
        ldsm4(qf[ks][0], qf[ks][1], qf[ks][2], qf[ks][3],
              uQ + 4u * ((wid * 16 + lrow) * AP + ks * 8 + lcol4));
    __syncthreads();

    float lacc[4] = {0.f, 0.f, 0.f, 0.f};    // row sums via ones-MMA
    float oacc[8][4];
#pragma unroll
    for (int i = 0; i < 8; i++)
#pragma unroll
        for (int r = 0; r < 4; r++) oacc[i][r] = 0.f;

    for (int kt = 0; kt < 32; kt++) {
        const int st = kt & 1;
        if (kt > 0) { CP_WAIT0(); __syncthreads(); }
        if (kt < 31) { LOAD_K(st ^ 1, kt + 1); LOAD_V(st ^ 1, kt + 1); CP_COMMIT(); }

        // ---- S = Q @ K^T (exp2-domain scores) ----
        float sacc[8][4];
#pragma unroll
        for (int i = 0; i < 8; i++)
#pragma unroll
            for (int r = 0; r < 4; r++) sacc[i][r] = 0.f;

#pragma unroll
        for (int ks = 0; ks < 4; ks++) {
#pragma unroll
            for (int np = 0; np < 4; np++) {
                uint32_t r0, r1, r2, r3;
                ldsm4(r0, r1, r2, r3,
                      uK[st] + 4u * ((np * 16 + lrow) * AP + ks * 8 + lcol4));
                mma16(sacc[2 * np],     qf[ks], r0, r2);
                mma16(sacc[2 * np + 1], qf[ks], r1, r3);
            }
        }

        // ---- P = exp2(S - POFF) straight into A-fragment registers ----
        // score C-frag (c0,c1)=row g cols 2t,2t+1 ; (c2,c3)=row g+8
        // == P@V A-frag for k16 chunk ks: a0,a1 from n-tile 2ks, a2,a3 from 2ks+1
#pragma unroll
        for (int ks = 0; ks < 4; ks++) {
            uint32_t pf[4];
            pf[0] = pexp2(sacc[2 * ks][0],     sacc[2 * ks][1]);
            pf[1] = pexp2(sacc[2 * ks][2],     sacc[2 * ks][3]);
            pf[2] = pexp2(sacc[2 * ks + 1][0], sacc[2 * ks + 1][1]);
            pf[3] = pexp2(sacc[2 * ks + 1][2], sacc[2 * ks + 1][3]);

            mma16(lacc, pf, ONES2, ONES2);   // row sums accumulate across all tiles

            // ---- O += P @ V  (V^T tile: [dk][key]) ----
#pragma unroll
            for (int np = 0; np < 4; np++) {
                uint32_t r0, r1, r2, r3;
                ldsm4(r0, r1, r2, r3,
                      uV[st] + 4u * ((np * 16 + lrow) * AP + ks * 8 + lcol4));
                mma16(oacc[2 * np],     pf, r0, r2);
                mma16(oacc[2 * np + 1], pf, r1, r3);
            }
        }
    }

    // ---- epilogue: lacc[0]=row g sum, lacc[2]=row g+8 sum ----
    const float inv0 = 1.f / lacc[0], inv1 = 1.f / lacc[2];
    const int b = bh >> 4, h = bh & 15;
    const int row0 = q0 + rbase;
    __half* base0 = Ctx + ((size_t)(b * 2048 + row0)) * 1024 + h * 64;
#pragma unroll
    for (int nt = 0; nt < 8; nt++) {
        const int col = nt * 8 + 2 * t;
        *(__half2*)(base0 + col) = __floats2half2_rn(oacc[nt][0] * inv0, oacc[nt][1] * inv0);
        *(__half2*)(base0 + 8 * 1024 + col) = __floats2half2_rn(oacc[nt][2] * inv1,
                                                                oacc[nt][3] * inv1);
    }
}

// ======================= fused prep: weights transpose + x convert ========
__global__ __launch_bounds__(256) void prep_all(
    const float* __restrict__ Wq, const float* __restrict__ Wk,
    const float* __restrict__ Wv, const float* __restrict__ Wo,
    const float* __restrict__ x,
    __half* __restrict__ Wh, __half* __restrict__ Woh, __half* __restrict__ xh)
{
    const int z = blockIdx.z;
    const int tx = threadIdx.x, ty = threadIdx.y;   // 32 x 8
    if (z == 4) {
        const int tl = (blockIdx.y * 32 + blockIdx.x) * 256 + ty * 32 + tx;
#pragma unroll
        for (int k = 0; k < 4; k++) {
            const int i = tl + k * 262144;
            float4 v = ((const float4*)x)[i];
            ((__half2*)xh)[2 * i]     = __floats2half2_rn(v.x, v.y);
            ((__half2*)xh)[2 * i + 1] = __floats2half2_rn(v.z, v.w);
        }
        return;
    }
    __shared__ float tb[32][33];
    const float* src = (z == 0) ? Wq : (z == 1) ? Wk : (z == 2) ? Wv : Wo;
    __half* dst = (z < 3) ? (Wh + (size_t)z * D_MOD * D_MOD) : Woh;
    const int k0 = blockIdx.x * 32, n0 = blockIdx.y * 32;
#pragma unroll
    for (int i = 0; i < 4; i++)
        tb[ty + i * 8][tx] = src[(size_t)(k0 + ty + i * 8) * D_MOD + n0 + tx];
    __syncthreads();
#pragma unroll
    for (int i = 0; i < 4; i++)
        dst[(size_t)(n0 + ty + i * 8) * D_MOD + k0 + tx] = __float2half_rn(tb[tx][ty + i * 8]);
}

// V [bh][s][64] -> Vt [bh][64][s], fp16
__global__ __launch_bounds__(256) void transpose_v(const __half* __restrict__ V,
                                                   __half* __restrict__ Vt) {
    __shared__ __half tb[32][36];
    const int bh = blockIdx.z;
    const int s0 = blockIdx.x * 32, d0 = blockIdx.y * 32;
    const int tx = threadIdx.x, ty = threadIdx.y;   // 32 x 8
    const __half* src = V + (size_t)bh * S_LEN * 64;
    __half* dst = Vt + (size_t)bh * 64 * S_LEN;
#pragma unroll
    for (int i = 0; i < 4; i++)
        tb[ty + i * 8][tx] = src[(size_t)(s0 + ty + i * 8) * 64 + d0 + tx];
    __syncthreads();
#pragma unroll
    for (int i = 0; i < 4; i++)
        dst[(size_t)(d0 + ty + i * 8) * S_LEN + s0 + tx] = tb[tx][ty + i * 8];
}

// ---------------- residual + LayerNorm ------------------------------------
__global__ __launch_bounds__(256) void ln_kernel(
    const float* __restrict__ x, const float* __restrict__ prj,
    const float* __restrict__ gamma, const float* __restrict__ beta,
    float* __restrict__ out)
{
    const int row = blockIdx.x;
    const int tid = threadIdx.x;

    const float4 xv = ((const float4*)(x   + (size_t)row * D_MOD))[tid];
    const float4 pv = ((const float4*)(prj + (size_t)row * D_MOD))[tid];
    float4 h;
    h.x = xv.x + pv.x; h.y = xv.y + pv.y; h.z = xv.z + pv.z; h.w = xv.w + pv.w;

    float sum = h.x + h.y + h.z + h.w;
    float ssq = h.x * h.x + h.y * h.y + h.z * h.z + h.w * h.w;
#pragma unroll
    for (int o = 16; o > 0; o >>= 1) {
        sum += __shfl_xor_sync(0xffffffffu, sum, o);
        ssq += __shfl_xor_sync(0xffffffffu, ssq, o);
    }
    __shared__ float rs[8], rq[8];
    const int warp = tid >> 5, lane = tid & 31;
    if (lane == 0) { rs[warp] = sum; rq[warp] = ssq; }
    __syncthreads();
    float ts = 0.f, tq = 0.f;
#pragma unroll
    for (int i = 0; i < 8; i++) { ts += rs[i]; tq += rq[i]; }

    const float mu   = ts * (1.f / (float)D_MOD);
    const float var  = tq * (1.f / (float)D_MOD) - mu * mu;
    const float rstd = rsqrtf(var + 1e-5f);

    const float4 gg = ((const float4*)gamma)[tid];
    const float4 bb = ((const float4*)beta)[tid];
    float4 o;
    o.x = (h.x - mu) * rstd * gg.x + bb.x;
    o.y = (h.y - mu) * rstd * gg.y + bb.y;
    o.z = (h.z - mu) * rstd * gg.z + bb.z;
    o.w = (h.w - mu) * rstd * gg.w + bb.w;
    ((float4*)(out + (size_t)row * D_MOD))[tid] = o;
}

// ---------------- launch ----------------------------------------------------
extern "C" void kernel_launch(void* const* d_in, const int* in_sizes, int n_in,
                              void* d_out, int out_size)
{
    const float* x  = (const float*)d_in[0];
    const float* Wq = (const float*)d_in[1];
    const float* bq = (const float*)d_in[2];
    const float* Wk = (const float*)d_in[3];
    const float* bk = (const float*)d_in[4];
    const float* Wv = (const float*)d_in[5];
    const float* bv = (const float*)d_in[6];
    const float* Wo = (const float*)d_in[7];
    const float* bo = (const float*)d_in[8];
    const float* ga = (const float*)d_in[9];
    const float* be = (const float*)d_in[10];
    float* out = (float*)d_out;

    __half *Xh, *Wh, *Woh, *Qp, *Kp, *Vp, *Vtp, *Ch;
    float *Pp;
    cudaGetSymbolAddress((void**)&Xh,  g_xh);
    cudaGetSymbolAddress((void**)&Wh,  g_Wh);
    cudaGetSymbolAddress((void**)&Woh, g_Woh);
    cudaGetSymbolAddress((void**)&Qp,  g_Q);
    cudaGetSymbolAddress((void**)&Kp,  g_K);
    cudaGetSymbolAddress((void**)&Vp,  g_V);
    cudaGetSymbolAddress((void**)&Vtp, g_Vt);
    cudaGetSymbolAddress((void**)&Ch,  g_ctxh);
    cudaGetSymbolAddress((void**)&Pp,  g_prj);

    cudaFuncSetAttribute(attn_h, cudaFuncAttributeMaxDynamicSharedMemorySize, ATTN_SMEM);

    prep_all<<<dim3(32, 32, 5), dim3(32, 8)>>>(Wq, Wk, Wv, Wo, x, Wh, Woh, Xh);

    gemm_h<1><<<dim3(24, 32), 256>>>(Xh, Wh, bq, bk, bv, Qp, Kp, Vp, nullptr);

    transpose_v<<<dim3(64, 2, NBH), dim3(32, 8)>>>(Vp, Vtp);

    attn_h<<<dim3(S_LEN / 128, NBH), 256, ATTN_SMEM>>>(Qp, Kp, Vtp, Ch);

    gemm_h<0><<<dim3(8, 32), 256>>>(Ch, Woh, bo, bo, bo, nullptr, nullptr, nullptr, Pp);

    ln_kernel<<<ROWS, 256>>>(x, Pp, ga, be, out);
}

// round 11
// speedup vs baseline: 1.1259x; 1.0004x over previous
#include <cuda_runtime.h>
#include <cuda_fp16.h>
#include <cstdint>
#include <math.h>

#define S_LEN 2048
#define D_MOD 1024
#define ROWS  4096          // B*S
#define NBH   32            // B*H
#define QSCALE 0.18033688011112042f   // 0.125 * log2(e)
#define POFF   8.0f                   // fixed exp2-domain offset (cancels in O/l)
#define ONES2  0x3C003C00u            // half2(1,1)

// ---------------- scratch (static; no allocations) ----------
__device__ __align__(128) __half g_xh [ROWS * D_MOD];
__device__ __align__(128) __half g_Wh [3 * D_MOD * D_MOD];    // [3072][1024] K-major fp16
__device__ __align__(128) __half g_Woh[D_MOD * D_MOD];
__device__ __align__(128) __half g_Q  [NBH * S_LEN * 64];     // pre-scaled by QSCALE
__device__ __align__(128) __half g_K  [NBH * S_LEN * 64];
__device__ __align__(128) __half g_V  [NBH * S_LEN * 64];
__device__ __align__(128) __half g_Vt [NBH * 64 * S_LEN];     // [bh][dk][s]
__device__ __align__(128) __half g_ctxh[ROWS * D_MOD];
__device__ __align__(128) float  g_prj[ROWS * D_MOD];

// ---------------- helpers ----------------
__device__ __forceinline__ uint32_t smem_u32(const void* p) {
    uint32_t a;
    asm("{ .reg .u64 t; cvta.to.shared.u64 t, %1; cvt.u32.u64 %0, t; }" : "=r"(a) : "l"(p));
    return a;
}
__device__ __forceinline__ void cp16(uint32_t dst, const void* src) {
    asm volatile("cp.async.cg.shared.global [%0], [%1], 16;" :: "r"(dst), "l"(src) : "memory");
}
#define CP_COMMIT() asm volatile("cp.async.commit_group;" ::: "memory")
#define CP_WAIT0()  asm volatile("cp.async.wait_group 0;" ::: "memory")
#define CP_WAIT1()  asm volatile("cp.async.wait_group 1;" ::: "memory")

// p = exp2(half2(a, b)) — POFF already folded into the MMA accumulator init
__device__ __forceinline__ uint32_t pexp2(float a, float b) {
    __half2 h = __floats2half2_rn(a, b);
    uint32_t u = *reinterpret_cast<uint32_t*>(&h);
    uint32_t r;
    asm("ex2.approx.f16x2 %0, %1;" : "=r"(r) : "r"(u));
    return r;
}
__device__ __forceinline__ void mma16(float* d, const uint32_t* a, uint32_t b0, uint32_t b1) {
    asm volatile("mma.sync.aligned.m16n8k16.row.col.f32.f16.f16.f32 "
        "{%0,%1,%2,%3}, {%4,%5,%6,%7}, {%8,%9}, {%0,%1,%2,%3};"
        : "+f"(d[0]), "+f"(d[1]), "+f"(d[2]), "+f"(d[3])
        : "r"(a[0]), "r"(a[1]), "r"(a[2]), "r"(a[3]), "r"(b0), "r"(b1));
}
__device__ __forceinline__ void ldsm4(uint32_t& r0, uint32_t& r1, uint32_t& r2, uint32_t& r3,
                                      uint32_t addr) {
    asm volatile("ldmatrix.sync.aligned.m8n8.x4.shared.b16 {%0,%1,%2,%3}, [%4];"
        : "=r"(r0), "=r"(r1), "=r"(r2), "=r"(r3) : "r"(addr));
}

// ======================= fp16 mma.sync GEMM (3-stage pipeline) =============
// C[4096, N] = A[4096,1024] @ W[N,1024]^T + bias.  BM=BN=128, BK=32 halves.
#define GPAD 20
#define GSTAGE_B  (128 * GPAD * 4)          // 10240 B per matrix per stage
#define GEMM_SMEM (3 * 2 * GSTAGE_B)        // 61440 B

template <int QKV>
__global__ __launch_bounds__(256, 2) void gemm_h(
    const __half* __restrict__ A, const __half* __restrict__ W,
    const float* __restrict__ b0, const float* __restrict__ b1, const float* __restrict__ b2,
    __half* __restrict__ hq, __half* __restrict__ hk, __half* __restrict__ hv,
    float* __restrict__ of)
{
    extern __shared__ uint32_t gsm[];
    const uint32_t sbase = smem_u32(gsm);

    const int tid = threadIdx.x;
    const int wid = tid >> 5, lane = tid & 31;
    const int g = lane >> 2, t = lane & 3;
    const int wm = wid & 1, wn = wid >> 1;       // warp 64 (M) x 32 (N)
    const int m0 = blockIdx.y * 128;
    const int n0 = blockIdx.x * 128;

    const int lrow  = (lane & 7) + ((lane >> 3) & 1) * 8;
    const int lcol4 = (lane >> 4) * 4;

    float acc[4][4][4];
#pragma unroll
    for (int i = 0; i < 4; i++)
#pragma unroll
        for (int j = 0; j < 4; j++)
#pragma unroll
            for (int r = 0; r < 4; r++) acc[i][j][r] = 0.f;

    // stage s: A at sbase + s*2*GSTAGE_B, B at +GSTAGE_B
#define G_LOAD(abase, bbase, kt) do {                                             \
    _Pragma("unroll")                                                             \
    for (int i = 0; i < 2; i++) {                                                 \
        int j = tid + i * 256;                                                    \
        int r = j >> 2, cq = j & 3;                                               \
        cp16((abase) + (uint32_t)(r * GPAD + cq * 4) * 4,                         \
             A + (size_t)(m0 + r) * 1024 + (kt) * 32 + cq * 8);                   \
        cp16((bbase) + (uint32_t)(r * GPAD + cq * 4) * 4,                         \
             W + (size_t)(n0 + r) * 1024 + (kt) * 32 + cq * 8);                   \
    }                                                                             \
    CP_COMMIT();                                                                  \
} while (0)

    G_LOAD(sbase, sbase + GSTAGE_B, 0);
    G_LOAD(sbase + 2 * GSTAGE_B, sbase + 3 * GSTAGE_B, 1);

    int st = 0;       // stage of tile kt
    int stl = 2;      // stage for tile kt+2
    for (int kt = 0; kt < 32; kt++) {
        if (kt < 31) { CP_WAIT1(); } else { CP_WAIT0(); }
        __syncthreads();
        if (kt + 2 < 32) {
            const uint32_t la = sbase + (uint32_t)stl * (2 * GSTAGE_B);
            G_LOAD(la, la + GSTAGE_B, kt + 2);
        }
        const uint32_t aoff = sbase + (uint32_t)st * (2 * GSTAGE_B);
        const uint32_t boff = aoff + GSTAGE_B;

#pragma unroll
        for (int ks = 0; ks < 2; ks++) {
            uint32_t af[4][4];
#pragma unroll
            for (int mt = 0; mt < 4; mt++)
                ldsm4(af[mt][0], af[mt][1], af[mt][2], af[mt][3],
                      aoff + 4u * ((wm * 64 + mt * 16 + lrow) * GPAD + ks * 8 + lcol4));
#pragma unroll
            for (int np = 0; np < 2; np++) {
                uint32_t r0, r1, r2, r3;
                ldsm4(r0, r1, r2, r3,
                      boff + 4u * ((wn * 32 + np * 16 + lrow) * GPAD + ks * 8 + lcol4));
#pragma unroll
                for (int mt = 0; mt < 4; mt++) {
                    mma16(acc[mt][2 * np],     af[mt], r0, r2);
                    mma16(acc[mt][2 * np + 1], af[mt], r1, r3);
                }
            }
        }
        if (++st == 3) st = 0;
        if (++stl == 3) stl = 0;
    }

    // epilogue
#pragma unroll
    for (int mt = 0; mt < 4; mt++) {
        const int r0 = m0 + wm * 64 + mt * 16 + g;
#pragma unroll
        for (int nt = 0; nt < 4; nt++) {
            const int col = n0 + wn * 32 + nt * 8 + 2 * t;
            if (QKV) {
                const int mat = col >> 10, nl = col & 1023;
                const float* bias = (mat == 0 ? b0 : mat == 1 ? b1 : b2);
                __half* op = (mat == 0 ? hq : mat == 1 ? hk : hv);
                const int h = nl >> 6, d = nl & 63;
                const float2 bv = *(const float2*)(bias + nl);
                const int b = r0 >> 11, s = r0 & 2047;
                __half* p = op + ((size_t)((b * 16 + h) * 2048 + s)) * 64 + d;
                float v0 = acc[mt][nt][0] + bv.x, v1 = acc[mt][nt][1] + bv.y;
                float v2 = acc[mt][nt][2] + bv.x, v3 = acc[mt][nt][3] + bv.y;
                if (mat == 0) { v0 *= QSCALE; v1 *= QSCALE; v2 *= QSCALE; v3 *= QSCALE; }
                *(__half2*)p = __floats2half2_rn(v0, v1);
                *(__half2*)(p + 8 * 64) = __floats2half2_rn(v2, v3);
            } else {
                const float2 bv = *(const float2*)(b0 + col);
                float* p = of + (size_t)r0 * 1024 + col;
                *(float2*)p = make_float2(acc[mt][nt][0] + bv.x, acc[mt][nt][1] + bv.y);
                *(float2*)(p + 8 * 1024) = make_float2(acc[mt][nt][2] + bv.x,
                                                       acc[mt][nt][3] + bv.y);
            }
        }
    }
}

// ======================= fp16 flash attention ==============================
// CTA: 128 queries, 8 warps (16 q-rows each). KV tiles of 64 keys.
// Q pre-scaled by 0.125*log2(e); sacc initialized to -POFF (folds the offset
// into the MMA accumulator); p = exp2(sacc); offset cancels in O/l.
#define AP   36
#define QU   (128 * AP)
#define KVU  (64 * AP)
#define ATTN_SMEM ((QU + 4 * KVU) * 4)   // 55296 bytes

__global__ __launch_bounds__(256, 2) void attn_h(
    const __half* __restrict__ Q, const __half* __restrict__ K,
    const __half* __restrict__ Vt, __half* __restrict__ Ctx)
{
    extern __shared__ uint32_t smu[];
    uint32_t* Qs = smu;
    uint32_t* Ks = smu + QU;
    uint32_t* Vs = smu + QU + 2 * KVU;

    const int bh = blockIdx.y;
    const int q0 = blockIdx.x * 128;
    const int tid = threadIdx.x;
    const int wid = tid >> 5, lane = tid & 31;
    const int g = lane >> 2, t = lane & 3;
    const int lrow  = (lane & 7) + ((lane >> 3) & 1) * 8;
    const int lcol4 = (lane >> 4) * 4;

    const __half* Qb = Q  + (size_t)bh * S_LEN * 64;
    const __half* Kb = K  + (size_t)bh * S_LEN * 64;
    const __half* Vb = Vt + (size_t)bh * 64 * S_LEN;

    const uint32_t uQ = smem_u32(Qs);
    const uint32_t uK[2] = {smem_u32(Ks), smem_u32(Ks + KVU)};
    const uint32_t uV[2] = {smem_u32(Vs), smem_u32(Vs + KVU)};

#define LOAD_K(st, kt) do { _Pragma("unroll") for (int i = 0; i < 2; i++) { \
    int j = tid + i * 256; int r = j >> 3, cq = j & 7;                      \
    cp16(uK[st] + (uint32_t)(r * AP + cq * 4) * 4,                          \
         Kb + (size_t)((kt) * 64 + r) * 64 + cq * 8); } } while (0)
#define LOAD_V(st, kt) do { _Pragma("unroll") for (int i = 0; i < 2; i++) { \
    int j = tid + i * 256; int r = j >> 3, cq = j & 7;                      \
    cp16(uV[st] + (uint32_t)(r * AP + cq * 4) * 4,                          \
         Vb + (size_t)r * S_LEN + (kt) * 64 + cq * 8); } } while (0)

    // prologue: Q + K0 + V0
#pragma unroll
    for (int i = 0; i < 4; i++) {
        int j = tid + i * 256; int r = j >> 3, cq = j & 7;
        cp16(uQ + (uint32_t)(r * AP + cq * 4) * 4, Qb + (size_t)(q0 + r) * 64 + cq * 8);
    }
    LOAD_K(0, 0); LOAD_V(0, 0); CP_COMMIT();
    CP_WAIT0();
    __syncthreads();

    const int rbase = wid * 16 + g;

    // hoist Q fragments (dk=64 -> 4 k16 steps)
    uint32_t qf[4][4];
#pragma unroll
    for (int ks = 0; ks < 4; ks++)
        ldsm4(qf[ks][0], qf[ks][1], qf[ks][2], qf[ks][3],
              uQ + 4u * ((wid * 16 + lrow) * AP + ks * 8 + lcol4));
    __syncthreads();

    float lacc[4] = {0.f, 0.f, 0.f, 0.f};    // row sums via ones-MMA
    float oacc[8][4];
#pragma unroll
    for (int i = 0; i < 8; i++)
#pragma unroll
        for (int r = 0; r < 4; r++) oacc[i][r] = 0.f;

    for (int kt = 0; kt < 32; kt++) {
        const int st = kt & 1;
        if (kt > 0) { CP_WAIT0(); __syncthreads(); }
        if (kt < 31) { LOAD_K(st ^ 1, kt + 1); LOAD_V(st ^ 1, kt + 1); CP_COMMIT(); }

        // ---- S = Q @ K^T - POFF  (offset folded into accumulator init) ----
        float sacc[8][4];
#pragma unroll
        for (int i = 0; i < 8; i++)
#pragma unroll
            for (int r = 0; r < 4; r++) sacc[i][r] = -POFF;

#pragma unroll
        for (int ks = 0; ks < 4; ks++) {
#pragma unroll
            for (int np = 0; np < 4; np++) {
                uint32_t r0, r1, r2, r3;
                ldsm4(r0, r1, r2, r3,
                      uK[st] + 4u * ((np * 16 + lrow) * AP + ks * 8 + lcol4));
                mma16(sacc[2 * np],     qf[ks], r0, r2);
                mma16(sacc[2 * np + 1], qf[ks], r1, r3);
            }
        }

        // ---- P = exp2(S) straight into A-fragment registers ----
#pragma unroll
        for (int ks = 0; ks < 4; ks++) {
            uint32_t pf[4];
            pf[0] = pexp2(sacc[2 * ks][0],     sacc[2 * ks][1]);
            pf[1] = pexp2(sacc[2 * ks][2],     sacc[2 * ks][3]);
            pf[2] = pexp2(sacc[2 * ks + 1][0], sacc[2 * ks + 1][1]);
            pf[3] = pexp2(sacc[2 * ks + 1][2], sacc[2 * ks + 1][3]);

            mma16(lacc, pf, ONES2, ONES2);   // row sums accumulate across all tiles

            // ---- O += P @ V  (V^T tile: [dk][key]) ----
#pragma unroll
            for (int np = 0; np < 4; np++) {
                uint32_t r0, r1, r2, r3;
                ldsm4(r0, r1, r2, r3,
                      uV[st] + 4u * ((np * 16 + lrow) * AP + ks * 8 + lcol4));
                mma16(oacc[2 * np],     pf, r0, r2);
                mma16(oacc[2 * np + 1], pf, r1, r3);
            }
        }
    }

    // ---- epilogue: lacc[0]=row g sum, lacc[2]=row g+8 sum ----
    const float inv0 = 1.f / lacc[0], inv1 = 1.f / lacc[2];
    const int b = bh >> 4, h = bh & 15;
    const int row0 = q0 + rbase;
    __half* base0 = Ctx + ((size_t)(b * 2048 + row0)) * 1024 + h * 64;
#pragma unroll
    for (int nt = 0; nt < 8; nt++) {
        const int col = nt * 8 + 2 * t;
        *(__half2*)(base0 + col) = __floats2half2_rn(oacc[nt][0] * inv0, oacc[nt][1] * inv0);
        *(__half2*)(base0 + 8 * 1024 + col) = __floats2half2_rn(oacc[nt][2] * inv1,
                                                                oacc[nt][3] * inv1);
    }
}

// ======================= fused prep: weights transpose + x convert ========
__global__ __launch_bounds__(256) void prep_all(
    const float* __restrict__ Wq, const float* __restrict__ Wk,
    const float* __restrict__ Wv, const float* __restrict__ Wo,
    const float* __restrict__ x,
    __half* __restrict__ Wh, __half* __restrict__ Woh, __half* __restrict__ xh)
{
    const int z = blockIdx.z;
    const int tx = threadIdx.x, ty = threadIdx.y;   // 32 x 8
    if (z == 4) {
        const int tl = (blockIdx.y * 32 + blockIdx.x) * 256 + ty * 32 + tx;
#pragma unroll
        for (int k = 0; k < 4; k++) {
            const int i = tl + k * 262144;
            float4 v = ((const float4*)x)[i];
            ((__half2*)xh)[2 * i]     = __floats2half2_rn(v.x, v.y);
            ((__half2*)xh)[2 * i + 1] = __floats2half2_rn(v.z, v.w);
        }
        return;
    }
    __shared__ float tb[32][33];
    const float* src = (z == 0) ? Wq : (z == 1) ? Wk : (z == 2) ? Wv : Wo;
    __half* dst = (z < 3) ? (Wh + (size_t)z * D_MOD * D_MOD) : Woh;
    const int k0 = blockIdx.x * 32, n0 = blockIdx.y * 32;
#pragma unroll
    for (int i = 0; i < 4; i++)
        tb[ty + i * 8][tx] = src[(size_t)(k0 + ty + i * 8) * D_MOD + n0 + tx];
    __syncthreads();
#pragma unroll
    for (int i = 0; i < 4; i++)
        dst[(size_t)(n0 + ty + i * 8) * D_MOD + k0 + tx] = __float2half_rn(tb[tx][ty + i * 8]);
}

// V [bh][s][64] -> Vt [bh][64][s], fp16
__global__ __launch_bounds__(256) void transpose_v(const __half* __restrict__ V,
                                                   __half* __restrict__ Vt) {
    __shared__ __half tb[32][36];
    const int bh = blockIdx.z;
    const int s0 = blockIdx.x * 32, d0 = blockIdx.y * 32;
    const int tx = threadIdx.x, ty = threadIdx.y;   // 32 x 8
    const __half* src = V + (size_t)bh * S_LEN * 64;
    __half* dst = Vt + (size_t)bh * 64 * S_LEN;
#pragma unroll
    for (int i = 0; i < 4; i++)
        tb[ty + i * 8][tx] = src[(size_t)(s0 + ty + i * 8) * 64 + d0 + tx];
    __syncthreads();
#pragma unroll
    for (int i = 0; i < 4; i++)
        dst[(size_t)(d0 + ty + i * 8) * S_LEN + s0 + tx] = tb[tx][ty + i * 8];
}

// ---------------- residual + LayerNorm ------------------------------------
__global__ __launch_bounds__(256) void ln_kernel(
    const float* __restrict__ x, const float* __restrict__ prj,
    const float* __restrict__ gamma, const float* __restrict__ beta,
    float* __restrict__ out)
{
    const int row = blockIdx.x;
    const int tid = threadIdx.x;

    const float4 xv = ((const float4*)(x   + (size_t)row * D_MOD))[tid];
    const float4 pv = ((const float4*)(prj + (size_t)row * D_MOD))[tid];
    float4 h;
    h.x = xv.x + pv.x; h.y = xv.y + pv.y; h.z = xv.z + pv.z; h.w = xv.w + pv.w;

    float sum = h.x + h.y + h.z + h.w;
    float ssq = h.x * h.x + h.y * h.y + h.z * h.z + h.w * h.w;
#pragma unroll
    for (int o = 16; o > 0; o >>= 1) {
        sum += __shfl_xor_sync(0xffffffffu, sum, o);
        ssq += __shfl_xor_sync(0xffffffffu, ssq, o);
    }
    __shared__ float rs[8], rq[8];
    const int warp = tid >> 5, lane = tid & 31;
    if (lane == 0) { rs[warp] = sum; rq[warp] = ssq; }
    __syncthreads();
    float ts = 0.f, tq = 0.f;
#pragma unroll
    for (int i = 0; i < 8; i++) { ts += rs[i]; tq += rq[i]; }

    const float mu   = ts * (1.f / (float)D_MOD);
    const float var  = tq * (1.f / (float)D_MOD) - mu * mu;
    const float rstd = rsqrtf(var + 1e-5f);

    const float4 gg = ((const float4*)gamma)[tid];
    const float4 bb = ((const float4*)beta)[tid];
    float4 o;
    o.x = (h.x - mu) * rstd * gg.x + bb.x;
    o.y = (h.y - mu) * rstd * gg.y + bb.y;
    o.z = (h.z - mu) * rstd * gg.z + bb.z;
    o.w = (h.w - mu) * rstd * gg.w + bb.w;
    ((float4*)(out + (size_t)row * D_MOD))[tid] = o;
}

// ---------------- launch ----------------------------------------------------
extern "C" void kernel_launch(void* const* d_in, const int* in_sizes, int n_in,
                              void* d_out, int out_size)
{
    const float* x  = (const float*)d_in[0];
    const float* Wq = (const float*)d_in[1];
    const float* bq = (const float*)d_in[2];
    const float* Wk = (const float*)d_in[3];
    const float* bk = (const float*)d_in[4];
    const float* Wv = (const float*)d_in[5];
    const float* bv = (const float*)d_in[6];
    const float* Wo = (const float*)d_in[7];
    const float* bo = (const float*)d_in[8];
    const float* ga = (const float*)d_in[9];
    const float* be = (const float*)d_in[10];
    float* out = (float*)d_out;

    __half *Xh, *Wh, *Woh, *Qp, *Kp, *Vp, *Vtp, *Ch;
    float *Pp;
    cudaGetSymbolAddress((void**)&Xh,  g_xh);
    cudaGetSymbolAddress((void**)&Wh,  g_Wh);
    cudaGetSymbolAddress((void**)&Woh, g_Woh);
    cudaGetSymbolAddress((void**)&Qp,  g_Q);
    cudaGetSymbolAddress((void**)&Kp,  g_K);
    cudaGetSymbolAddress((void**)&Vp,  g_V);
    cudaGetSymbolAddress((void**)&Vtp, g_Vt);
    cudaGetSymbolAddress((void**)&Ch,  g_ctxh);
    cudaGetSymbolAddress((void**)&Pp,  g_prj);

    cudaFuncSetAttribute(attn_h, cudaFuncAttributeMaxDynamicSharedMemorySize, ATTN_SMEM);
    cudaFuncSetAttribute(gemm_h<1>, cudaFuncAttributeMaxDynamicSharedMemorySize, GEMM_SMEM);
    cudaFuncSetAttribute(gemm_h<0>, cudaFuncAttributeMaxDynamicSharedMemorySize, GEMM_SMEM);

    prep_all<<<dim3(32, 32, 5), dim3(32, 8)>>>(Wq, Wk, Wv, Wo, x, Wh, Woh, Xh);

    gemm_h<1><<<dim3(24, 32), 256, GEMM_SMEM>>>(Xh, Wh, bq, bk, bv, Qp, Kp, Vp, nullptr);

    transpose_v<<<dim3(64, 2, NBH), dim3(32, 8)>>>(Vp, Vtp);

    attn_h<<<dim3(S_LEN / 128, NBH), 256, ATTN_SMEM>>>(Qp, Kp, Vtp, Ch);

    gemm_h<0><<<dim3(8, 32), 256, GEMM_SMEM>>>(Ch, Woh, bo, bo, bo, nullptr, nullptr, nullptr, Pp);

    ln_kernel<<<ROWS, 256>>>(x, Pp, ga, be, out);
}

// round 12
// speedup vs baseline: 1.1623x; 1.0324x over previous
#include <cuda_runtime.h>
#include <cuda_fp16.h>
#include <cstdint>
#include <math.h>

#define S_LEN 2048
#define D_MOD 1024
#define ROWS  4096          // B*S
#define NBH   32            // B*H
#define QSCALE 0.18033688011112042f   // 0.125 * log2(e)
#define POFF   8.0f                   // fixed exp2-domain offset (cancels in O/l)
#define ONES2  0x3C003C00u            // half2(1,1)

// ---------------- scratch (static; no allocations) ----------
__device__ __align__(128) __half g_xh [ROWS * D_MOD];
__device__ __align__(128) __half g_Wh [3 * D_MOD * D_MOD];    // [3072][1024] K-major fp16
__device__ __align__(128) __half g_Woh[D_MOD * D_MOD];
__device__ __align__(128) __half g_Q  [NBH * S_LEN * 64];     // pre-scaled by QSCALE
__device__ __align__(128) __half g_K  [NBH * S_LEN * 64];
__device__ __align__(128) __half g_Vt [NBH * 64 * S_LEN];     // [bh][dk][s] (written by GEMM)
__device__ __align__(128) __half g_ctxh[ROWS * D_MOD];
__device__ __align__(128) float  g_prj[ROWS * D_MOD];

// ---------------- helpers ----------------
__device__ __forceinline__ uint32_t smem_u32(const void* p) {
    uint32_t a;
    asm("{ .reg .u64 t; cvta.to.shared.u64 t, %1; cvt.u32.u64 %0, t; }" : "=r"(a) : "l"(p));
    return a;
}
__device__ __forceinline__ void cp16(uint32_t dst, const void* src) {
    asm volatile("cp.async.cg.shared.global [%0], [%1], 16;" :: "r"(dst), "l"(src) : "memory");
}
#define CP_COMMIT() asm volatile("cp.async.commit_group;" ::: "memory")
#define CP_WAIT0()  asm volatile("cp.async.wait_group 0;" ::: "memory")
#define CP_WAIT1()  asm volatile("cp.async.wait_group 1;" ::: "memory")

// p = exp2(half2(a, b)) — POFF already folded into the MMA accumulator init
__device__ __forceinline__ uint32_t pexp2(float a, float b) {
    __half2 h = __floats2half2_rn(a, b);
    uint32_t u = *reinterpret_cast<uint32_t*>(&h);
    uint32_t r;
    asm("ex2.approx.f16x2 %0, %1;" : "=r"(r) : "r"(u));
    return r;
}
__device__ __forceinline__ void mma16(float* d, const uint32_t* a, uint32_t b0, uint32_t b1) {
    asm volatile("mma.sync.aligned.m16n8k16.row.col.f32.f16.f16.f32 "
        "{%0,%1,%2,%3}, {%4,%5,%6,%7}, {%8,%9}, {%0,%1,%2,%3};"
        : "+f"(d[0]), "+f"(d[1]), "+f"(d[2]), "+f"(d[3])
        : "r"(a[0]), "r"(a[1]), "r"(a[2]), "r"(a[3]), "r"(b0), "r"(b1));
}
__device__ __forceinline__ void ldsm4(uint32_t& r0, uint32_t& r1, uint32_t& r2, uint32_t& r3,
                                      uint32_t addr) {
    asm volatile("ldmatrix.sync.aligned.m8n8.x4.shared.b16 {%0,%1,%2,%3}, [%4];"
        : "=r"(r0), "=r"(r1), "=r"(r2), "=r"(r3) : "r"(addr));
}

// ======================= fp16 mma.sync GEMM (3-stage pipeline) =============
// C[4096, N] = A[4096,1024] @ W[N,1024]^T + bias.  BM=BN=128, BK=32 halves.
// QKV=1: Q/K written [B,H,S,64] (Q pre-scaled); V written TRANSPOSED [bh][dk][s].
#define GPAD 20
#define GSTAGE_B  (128 * GPAD * 4)          // 10240 B per matrix per stage
#define GEMM_SMEM (3 * 2 * GSTAGE_B)        // 61440 B

template <int QKV>
__global__ __launch_bounds__(256, 2) void gemm_h(
    const __half* __restrict__ A, const __half* __restrict__ W,
    const float* __restrict__ b0, const float* __restrict__ b1, const float* __restrict__ b2,
    __half* __restrict__ hq, __half* __restrict__ hk, __half* __restrict__ hvt,
    float* __restrict__ of)
{
    extern __shared__ uint32_t gsm[];
    const uint32_t sbase = smem_u32(gsm);

    const int tid = threadIdx.x;
    const int wid = tid >> 5, lane = tid & 31;
    const int g = lane >> 2, t = lane & 3;
    const int wm = wid & 1, wn = wid >> 1;       // warp 64 (M) x 32 (N)
    const int m0 = blockIdx.y * 128;
    const int n0 = blockIdx.x * 128;

    const int lrow  = (lane & 7) + ((lane >> 3) & 1) * 8;
    const int lcol4 = (lane >> 4) * 4;

    float acc[4][4][4];
#pragma unroll
    for (int i = 0; i < 4; i++)
#pragma unroll
        for (int j = 0; j < 4; j++)
#pragma unroll
            for (int r = 0; r < 4; r++) acc[i][j][r] = 0.f;

#define G_LOAD(abase, bbase, kt) do {                                             \
    _Pragma("unroll")                                                             \
    for (int i = 0; i < 2; i++) {                                                 \
        int j = tid + i * 256;                                                    \
        int r = j >> 2, cq = j & 3;                                               \
        cp16((abase) + (uint32_t)(r * GPAD + cq * 4) * 4,                         \
             A + (size_t)(m0 + r) * 1024 + (kt) * 32 + cq * 8);                   \
        cp16((bbase) + (uint32_t)(r * GPAD + cq * 4) * 4,                         \
             W + (size_t)(n0 + r) * 1024 + (kt) * 32 + cq * 8);                   \
    }                                                                             \
    CP_COMMIT();                                                                  \
} while (0)

    G_LOAD(sbase, sbase + GSTAGE_B, 0);
    G_LOAD(sbase + 2 * GSTAGE_B, sbase + 3 * GSTAGE_B, 1);

    int st = 0;
    int stl = 2;
    for (int kt = 0; kt < 32; kt++) {
        if (kt < 31) { CP_WAIT1(); } else { CP_WAIT0(); }
        __syncthreads();
        if (kt + 2 < 32) {
            const uint32_t la = sbase + (uint32_t)stl * (2 * GSTAGE_B);
            G_LOAD(la, la + GSTAGE_B, kt + 2);
        }
        const uint32_t aoff = sbase + (uint32_t)st * (2 * GSTAGE_B);
        const uint32_t boff = aoff + GSTAGE_B;

#pragma unroll
        for (int ks = 0; ks < 2; ks++) {
            uint32_t af[4][4];
#pragma unroll
            for (int mt = 0; mt < 4; mt++)
                ldsm4(af[mt][0], af[mt][1], af[mt][2], af[mt][3],
                      aoff + 4u * ((wm * 64 + mt * 16 + lrow) * GPAD + ks * 8 + lcol4));
#pragma unroll
            for (int np = 0; np < 2; np++) {
                uint32_t r0, r1, r2, r3;
                ldsm4(r0, r1, r2, r3,
                      boff + 4u * ((wn * 32 + np * 16 + lrow) * GPAD + ks * 8 + lcol4));
#pragma unroll
                for (int mt = 0; mt < 4; mt++) {
                    mma16(acc[mt][2 * np],     af[mt], r0, r2);
                    mma16(acc[mt][2 * np + 1], af[mt], r1, r3);
                }
            }
        }
        if (++st == 3) st = 0;
        if (++stl == 3) stl = 0;
    }

    // epilogue
#pragma unroll
    for (int mt = 0; mt < 4; mt++) {
        const int r0 = m0 + wm * 64 + mt * 16 + g;
#pragma unroll
        for (int nt = 0; nt < 4; nt++) {
            const int col = n0 + wn * 32 + nt * 8 + 2 * t;
            if (QKV) {
                const int mat = col >> 10, nl = col & 1023;
                const float* bias = (mat == 0 ? b0 : mat == 1 ? b1 : b2);
                const int h = nl >> 6, d = nl & 63;
                const float2 bv = *(const float2*)(bias + nl);
                const int b = r0 >> 11, s = r0 & 2047;
                float v0 = acc[mt][nt][0] + bv.x, v1 = acc[mt][nt][1] + bv.y;
                float v2 = acc[mt][nt][2] + bv.x, v3 = acc[mt][nt][3] + bv.y;
                if (mat == 0) {
                    v0 *= QSCALE; v1 *= QSCALE; v2 *= QSCALE; v3 *= QSCALE;
                    __half* p = hq + ((size_t)((b * 16 + h) * 2048 + s)) * 64 + d;
                    *(__half2*)p = __floats2half2_rn(v0, v1);
                    *(__half2*)(p + 8 * 64) = __floats2half2_rn(v2, v3);
                } else if (mat == 1) {
                    __half* p = hk + ((size_t)((b * 16 + h) * 2048 + s)) * 64 + d;
                    *(__half2*)p = __floats2half2_rn(v0, v1);
                    *(__half2*)(p + 8 * 64) = __floats2half2_rn(v2, v3);
                } else {
                    // V: write transposed [bh][dk][s]
                    __half* vp = hvt + (size_t)(b * 16 + h) * 64 * S_LEN;
                    vp[(size_t)d * S_LEN + s]           = __float2half_rn(v0);
                    vp[(size_t)(d + 1) * S_LEN + s]     = __float2half_rn(v1);
                    vp[(size_t)d * S_LEN + s + 8]       = __float2half_rn(v2);
                    vp[(size_t)(d + 1) * S_LEN + s + 8] = __float2half_rn(v3);
                }
            } else {
                const float2 bv = *(const float2*)(b0 + col);
                float* p = of + (size_t)r0 * 1024 + col;
                *(float2*)p = make_float2(acc[mt][nt][0] + bv.x, acc[mt][nt][1] + bv.y);
                *(float2*)(p + 8 * 1024) = make_float2(acc[mt][nt][2] + bv.x,
                                                       acc[mt][nt][3] + bv.y);
            }
        }
    }
}

// ======================= fp16 flash attention ==============================
// CTA: 128 queries, 8 warps. KV tiles of 128 keys, processed in two 64-key
// halves (same register footprint, half the barriers). P in registers,
// l via ones-MMA, POFF folded into accumulator init.
#define APK  36                  // K row pitch: 64 halves + pad (u32)
#define APV  68                  // V row pitch: 128 halves + pad (u32)
#define QU   (128 * APK)         // 4608 u32
#define KU   (128 * APK)         // 4608 u32 per stage
#define VU   (64 * APV)          // 4352 u32 per stage
#define ATTN_SMEM ((QU + 2 * KU + 2 * VU) * 4)   // 90112 bytes

__global__ __launch_bounds__(256, 2) void attn_h(
    const __half* __restrict__ Q, const __half* __restrict__ K,
    const __half* __restrict__ Vt, __half* __restrict__ Ctx)
{
    extern __shared__ uint32_t smu[];
    const uint32_t uQ = smem_u32(smu);
    const uint32_t uK[2] = {uQ + 4u * QU, uQ + 4u * (QU + KU)};
    const uint32_t uV[2] = {uQ + 4u * (QU + 2 * KU), uQ + 4u * (QU + 2 * KU + VU)};

    const int bh = blockIdx.y;
    const int q0 = blockIdx.x * 128;
    const int tid = threadIdx.x;
    const int wid = tid >> 5, lane = tid & 31;
    const int g = lane >> 2, t = lane & 3;
    const int lrow  = (lane & 7) + ((lane >> 3) & 1) * 8;
    const int lcol4 = (lane >> 4) * 4;

    const __half* Qb = Q  + (size_t)bh * S_LEN * 64;
    const __half* Kb = K  + (size_t)bh * S_LEN * 64;
    const __half* Vb = Vt + (size_t)bh * 64 * S_LEN;

    // K tile: 128 rows x 64 halves; V tile: 64 rows x 128 halves (transposed gmem)
#define LOAD_K(st, kt) do { _Pragma("unroll") for (int i = 0; i < 4; i++) { \
    int j = tid + i * 256; int r = j >> 3, cq = j & 7;                      \
    cp16(uK[st] + (uint32_t)(r * APK + cq * 4) * 4,                         \
         Kb + (size_t)((kt) * 128 + r) * 64 + cq * 8); } } while (0)
#define LOAD_V(st, kt) do { _Pragma("unroll") for (int i = 0; i < 4; i++) { \
    int j = tid + i * 256; int r = j >> 4, cq = j & 15;                     \
    cp16(uV[st] + (uint32_t)(r * APV + cq * 4) * 4,                         \
         Vb + (size_t)r * S_LEN + (kt) * 128 + cq * 8); } } while (0)

    // prologue: Q + K0 + V0
#pragma unroll
    for (int i = 0; i < 4; i++) {
        int j = tid + i * 256; int r = j >> 3, cq = j & 7;
        cp16(uQ + (uint32_t)(r * APK + cq * 4) * 4, Qb + (size_t)(q0 + r) * 64 + cq * 8);
    }
    LOAD_K(0, 0); LOAD_V(0, 0); CP_COMMIT();
    CP_WAIT0();
    __syncthreads();

    const int rbase = wid * 16 + g;

    // hoist Q fragments (dk=64 -> 4 k16 steps)
    uint32_t qf[4][4];
#pragma unroll
    for (int ks = 0; ks < 4; ks++)
        ldsm4(qf[ks][0], qf[ks][1], qf[ks][2], qf[ks][3],
              uQ + 4u * ((wid * 16 + lrow) * APK + ks * 8 + lcol4));

    float lacc[4] = {0.f, 0.f, 0.f, 0.f};
    float oacc[8][4];
#pragma unroll
    for (int i = 0; i < 8; i++)
#pragma unroll
        for (int r = 0; r < 4; r++) oacc[i][r] = 0.f;

    for (int kt = 0; kt < 16; kt++) {
        const int st = kt & 1;
        if (kt > 0) { CP_WAIT0(); __syncthreads(); }
        if (kt < 15) { LOAD_K(st ^ 1, kt + 1); LOAD_V(st ^ 1, kt + 1); CP_COMMIT(); }

        // two 64-key halves per tile
#pragma unroll
        for (int hf = 0; hf < 2; hf++) {
            // ---- S = Q @ K^T - POFF ----
            float sacc[8][4];
#pragma unroll
            for (int i = 0; i < 8; i++)
#pragma unroll
                for (int r = 0; r < 4; r++) sacc[i][r] = -POFF;

#pragma unroll
            for (int ks = 0; ks < 4; ks++) {
#pragma unroll
                for (int np = 0; np < 4; np++) {
                    uint32_t r0, r1, r2, r3;
                    ldsm4(r0, r1, r2, r3,
                          uK[st] + 4u * ((hf * 64 + np * 16 + lrow) * APK + ks * 8 + lcol4));
                    mma16(sacc[2 * np],     qf[ks], r0, r2);
                    mma16(sacc[2 * np + 1], qf[ks], r1, r3);
                }
            }

            // ---- P = exp2(S) into A-fragment registers; O += P @ V ----
#pragma unroll
            for (int ks = 0; ks < 4; ks++) {
                uint32_t pf[4];
                pf[0] = pexp2(sacc[2 * ks][0],     sacc[2 * ks][1]);
                pf[1] = pexp2(sacc[2 * ks][2],     sacc[2 * ks][3]);
                pf[2] = pexp2(sacc[2 * ks + 1][0], sacc[2 * ks + 1][1]);
                pf[3] = pexp2(sacc[2 * ks + 1][2], sacc[2 * ks + 1][3]);

                mma16(lacc, pf, ONES2, ONES2);

#pragma unroll
                for (int np = 0; np < 4; np++) {
                    uint32_t r0, r1, r2, r3;
                    ldsm4(r0, r1, r2, r3,
                          uV[st] + 4u * ((np * 16 + lrow) * APV + hf * 32 + ks * 8 + lcol4));
                    mma16(oacc[2 * np],     pf, r0, r2);
                    mma16(oacc[2 * np + 1], pf, r1, r3);
                }
            }
        }
    }

    // ---- epilogue: lacc[0]=row g sum, lacc[2]=row g+8 sum ----
    const float inv0 = 1.f / lacc[0], inv1 = 1.f / lacc[2];
    const int b = bh >> 4, h = bh & 15;
    const int row0 = q0 + rbase;
    __half* base0 = Ctx + ((size_t)(b * 2048 + row0)) * 1024 + h * 64;
#pragma unroll
    for (int nt = 0; nt < 8; nt++) {
        const int col = nt * 8 + 2 * t;
        *(__half2*)(base0 + col) = __floats2half2_rn(oacc[nt][0] * inv0, oacc[nt][1] * inv0);
        *(__half2*)(base0 + 8 * 1024 + col) = __floats2half2_rn(oacc[nt][2] * inv1,
                                                                oacc[nt][3] * inv1);
    }
}

// ======================= fused prep: weights transpose + x convert ========
__global__ __launch_bounds__(256) void prep_all(
    const float* __restrict__ Wq, const float* __restrict__ Wk,
    const float* __restrict__ Wv, const float* __restrict__ Wo,
    const float* __restrict__ x,
    __half* __restrict__ Wh, __half* __restrict__ Woh, __half* __restrict__ xh)
{
    const int z = blockIdx.z;
    const int tx = threadIdx.x, ty = threadIdx.y;   // 32 x 8
    if (z == 4) {
        const int tl = (blockIdx.y * 32 + blockIdx.x) * 256 + ty * 32 + tx;
#pragma unroll
        for (int k = 0; k < 4; k++) {
            const int i = tl + k * 262144;
            float4 v = ((const float4*)x)[i];
            ((__half2*)xh)[2 * i]     = __floats2half2_rn(v.x, v.y);
            ((__half2*)xh)[2 * i + 1] = __floats2half2_rn(v.z, v.w);
        }
        return;
    }
    __shared__ float tb[32][33];
    const float* src = (z == 0) ? Wq : (z == 1) ? Wk : (z == 2) ? Wv : Wo;
    __half* dst = (z < 3) ? (Wh + (size_t)z * D_MOD * D_MOD) : Woh;
    const int k0 = blockIdx.x * 32, n0 = blockIdx.y * 32;
#pragma unroll
    for (int i = 0; i < 4; i++)
        tb[ty + i * 8][tx] = src[(size_t)(k0 + ty + i * 8) * D_MOD + n0 + tx];
    __syncthreads();
#pragma unroll
    for (int i = 0; i < 4; i++)
        dst[(size_t)(n0 + ty + i * 8) * D_MOD + k0 + tx] = __float2half_rn(tb[tx][ty + i * 8]);
}

// ---------------- residual + LayerNorm ------------------------------------
__global__ __launch_bounds__(256) void ln_kernel(
    const float* __restrict__ x, const float* __restrict__ prj,
    const float* __restrict__ gamma, const float* __restrict__ beta,
    float* __restrict__ out)
{
    const int row = blockIdx.x;
    const int tid = threadIdx.x;

    const float4 xv = ((const float4*)(x   + (size_t)row * D_MOD))[tid];
    const float4 pv = ((const float4*)(prj + (size_t)row * D_MOD))[tid];
    float4 h;
    h.x = xv.x + pv.x; h.y = xv.y + pv.y; h.z = xv.z + pv.z; h.w = xv.w + pv.w;

    float sum = h.x + h.y + h.z + h.w;
    float ssq = h.x * h.x + h.y * h.y + h.z * h.z + h.w * h.w;
#pragma unroll
    for (int o = 16; o > 0; o >>= 1) {
        sum += __shfl_xor_sync(0xffffffffu, sum, o);
        ssq += __shfl_xor_sync(0xffffffffu, ssq, o);
    }
    __shared__ float rs[8], rq[8];
    const int warp = tid >> 5, lane = tid & 31;
    if (lane == 0) { rs[warp] = sum; rq[warp] = ssq; }
    __syncthreads();
    float ts = 0.f, tq = 0.f;
#pragma unroll
    for (int i = 0; i < 8; i++) { ts += rs[i]; tq += rq[i]; }

    const float mu   = ts * (1.f / (float)D_MOD);
    const float var  = tq * (1.f / (float)D_MOD) - mu * mu;
    const float rstd = rsqrtf(var + 1e-5f);

    const float4 gg = ((const float4*)gamma)[tid];
    const float4 bb = ((const float4*)beta)[tid];
    float4 o;
    o.x = (h.x - mu) * rstd * gg.x + bb.x;
    o.y = (h.y - mu) * rstd * gg.y + bb.y;
    o.z = (h.z - mu) * rstd * gg.z + bb.z;
    o.w = (h.w - mu) * rstd * gg.w + bb.w;
    ((float4*)(out + (size_t)row * D_MOD))[tid] = o;
}

// ---------------- launch ----------------------------------------------------
extern "C" void kernel_launch(void* const* d_in, const int* in_sizes, int n_in,
                              void* d_out, int out_size)
{
    const float* x  = (const float*)d_in[0];
    const float* Wq = (const float*)d_in[1];
    const float* bq = (const float*)d_in[2];
    const float* Wk = (const float*)d_in[3];
    const float* bk = (const float*)d_in[4];
    const float* Wv = (const float*)d_in[5];
    const float* bv = (const float*)d_in[6];
    const float* Wo = (const float*)d_in[7];
    const float* bo = (const float*)d_in[8];
    const float* ga = (const float*)d_in[9];
    const float* be = (const float*)d_in[10];
    float* out = (float*)d_out;

    __half *Xh, *Wh, *Woh, *Qp, *Kp, *Vtp, *Ch;
    float *Pp;
    cudaGetSymbolAddress((void**)&Xh,  g_xh);
    cudaGetSymbolAddress((void**)&Wh,  g_Wh);
    cudaGetSymbolAddress((void**)&Woh, g_Woh);
    cudaGetSymbolAddress((void**)&Qp,  g_Q);
    cudaGetSymbolAddress((void**)&Kp,  g_K);
    cudaGetSymbolAddress((void**)&Vtp, g_Vt);
    cudaGetSymbolAddress((void**)&Ch,  g_ctxh);
    cudaGetSymbolAddress((void**)&Pp,  g_prj);

    cudaFuncSetAttribute(attn_h, cudaFuncAttributeMaxDynamicSharedMemorySize, ATTN_SMEM);
    cudaFuncSetAttribute(gemm_h<1>, cudaFuncAttributeMaxDynamicSharedMemorySize, GEMM_SMEM);
    cudaFuncSetAttribute(gemm_h<0>, cudaFuncAttributeMaxDynamicSharedMemorySize, GEMM_SMEM);

    prep_all<<<dim3(32, 32, 5), dim3(32, 8)>>>(Wq, Wk, Wv, Wo, x, Wh, Woh, Xh);

    gemm_h<1><<<dim3(24, 32), 256, GEMM_SMEM>>>(Xh, Wh, bq, bk, bv, Qp, Kp, Vtp, nullptr);

    attn_h<<<dim3(S_LEN / 128, NBH), 256, ATTN_SMEM>>>(Qp, Kp, Vtp, Ch);

    gemm_h<0><<<dim3(8, 32), 256, GEMM_SMEM>>>(Ch, Woh, bo, bo, bo, nullptr, nullptr, nullptr, Pp);

    ln_kernel<<<ROWS, 256>>>(x, Pp, ga, be, out);
}

// round 13
// speedup vs baseline: 1.2161x; 1.0463x over previous
#include <cuda_runtime.h>
#include <cuda_fp16.h>
#include <cstdint>
#include <math.h>

#define S_LEN 2048
#define D_MOD 1024
#define ROWS  4096          // B*S
#define NBH   32            // B*H
#define QSCALE 0.18033688011112042f   // 0.125 * log2(e)
#define POFF   8.0f                   // fixed exp2-domain offset (cancels in O/l)
#define ONES2  0x3C003C00u            // half2(1,1)

// ---------------- scratch (static; no allocations) ----------
__device__ __align__(128) __half g_xh [ROWS * D_MOD];
__device__ __align__(128) __half g_Wh [3 * D_MOD * D_MOD];    // [3072][1024] K-major fp16
__device__ __align__(128) __half g_Woh[D_MOD * D_MOD];
__device__ __align__(128) __half g_Q  [NBH * S_LEN * 64];     // pre-scaled by QSCALE
__device__ __align__(128) __half g_K  [NBH * S_LEN * 64];
__device__ __align__(128) __half g_Vt [NBH * 64 * S_LEN];     // [bh][dk][s] (written by GEMM)
__device__ __align__(128) __half g_ctxh[ROWS * D_MOD];
__device__ __align__(128) float  g_prj[ROWS * D_MOD];         // x + ctx@Wo + bo (residual fused)

// ---------------- helpers ----------------
__device__ __forceinline__ uint32_t smem_u32(const void* p) {
    uint32_t a;
    asm("{ .reg .u64 t; cvta.to.shared.u64 t, %1; cvt.u32.u64 %0, t; }" : "=r"(a) : "l"(p));
    return a;
}
__device__ __forceinline__ void cp16(uint32_t dst, const void* src) {
    asm volatile("cp.async.cg.shared.global [%0], [%1], 16;" :: "r"(dst), "l"(src) : "memory");
}
#define CP_COMMIT() asm volatile("cp.async.commit_group;" ::: "memory")
#define CP_WAIT0()  asm volatile("cp.async.wait_group 0;" ::: "memory")
#define CP_WAIT1()  asm volatile("cp.async.wait_group 1;" ::: "memory")

// p = exp2(half2(a, b)) — POFF already folded into the MMA accumulator init
__device__ __forceinline__ uint32_t pexp2(float a, float b) {
    __half2 h = __floats2half2_rn(a, b);
    uint32_t u = *reinterpret_cast<uint32_t*>(&h);
    uint32_t r;
    asm("ex2.approx.f16x2 %0, %1;" : "=r"(r) : "r"(u));
    return r;
}
__device__ __forceinline__ void mma16(float* d, const uint32_t* a, uint32_t b0, uint32_t b1) {
    asm volatile("mma.sync.aligned.m16n8k16.row.col.f32.f16.f16.f32 "
        "{%0,%1,%2,%3}, {%4,%5,%6,%7}, {%8,%9}, {%0,%1,%2,%3};"
        : "+f"(d[0]), "+f"(d[1]), "+f"(d[2]), "+f"(d[3])
        : "r"(a[0]), "r"(a[1]), "r"(a[2]), "r"(a[3]), "r"(b0), "r"(b1));
}
__device__ __forceinline__ void ldsm4(uint32_t& r0, uint32_t& r1, uint32_t& r2, uint32_t& r3,
                                      uint32_t addr) {
    asm volatile("ldmatrix.sync.aligned.m8n8.x4.shared.b16 {%0,%1,%2,%3}, [%4];"
        : "=r"(r0), "=r"(r1), "=r"(r2), "=r"(r3) : "r"(addr));
}

// ======================= fp16 mma.sync GEMM (BK=64, 3-stage) ===============
// C[4096, N] = A[4096,1024] @ W[N,1024]^T + bias.  BM=BN=128, BK=64 halves.
// QKV=1: Q/K written [B,H,S,64] (Q pre-scaled); V written TRANSPOSED [bh][dk][s].
// QKV=0: writes float prj = acc + bias + x (residual fused).
#define GPAD2 36                               // 32 data u32 + 4 pad
#define GSTAGE_B  (128 * GPAD2 * 4)            // 18432 B per matrix per stage
#define GEMM_SMEM (3 * 2 * GSTAGE_B)           // 110592 B

template <int QKV>
__global__ __launch_bounds__(256, 2) void gemm_h(
    const __half* __restrict__ A, const __half* __restrict__ W,
    const float* __restrict__ b0, const float* __restrict__ b1, const float* __restrict__ b2,
    __half* __restrict__ hq, __half* __restrict__ hk, __half* __restrict__ hvt,
    const float* __restrict__ xres, float* __restrict__ of)
{
    extern __shared__ uint32_t gsm[];
    const uint32_t sbase = smem_u32(gsm);

    const int tid = threadIdx.x;
    const int wid = tid >> 5, lane = tid & 31;
    const int g = lane >> 2, t = lane & 3;
    const int wm = wid & 1, wn = wid >> 1;       // warp 64 (M) x 32 (N)
    const int m0 = blockIdx.y * 128;
    const int n0 = blockIdx.x * 128;

    const int lrow  = (lane & 7) + ((lane >> 3) & 1) * 8;
    const int lcol4 = (lane >> 4) * 4;

    float acc[4][4][4];
#pragma unroll
    for (int i = 0; i < 4; i++)
#pragma unroll
        for (int j = 0; j < 4; j++)
#pragma unroll
            for (int r = 0; r < 4; r++) acc[i][j][r] = 0.f;

    // 128 rows x 64 halves per matrix: 1024 cp16 -> 4 per thread
#define G_LOAD(abase, bbase, kt) do {                                             \
    _Pragma("unroll")                                                             \
    for (int i = 0; i < 4; i++) {                                                 \
        int j = tid + i * 256;                                                    \
        int r = j >> 3, cq = j & 7;                                               \
        cp16((abase) + (uint32_t)(r * GPAD2 + cq * 4) * 4,                        \
             A + (size_t)(m0 + r) * 1024 + (kt) * 64 + cq * 8);                   \
        cp16((bbase) + (uint32_t)(r * GPAD2 + cq * 4) * 4,                        \
             W + (size_t)(n0 + r) * 1024 + (kt) * 64 + cq * 8);                   \
    }                                                                             \
    CP_COMMIT();                                                                  \
} while (0)

    G_LOAD(sbase, sbase + GSTAGE_B, 0);
    G_LOAD(sbase + 2 * GSTAGE_B, sbase + 3 * GSTAGE_B, 1);

    int st = 0;       // stage of tile kt
    int stl = 2;      // stage for tile kt+2
    for (int kt = 0; kt < 16; kt++) {
        if (kt < 15) { CP_WAIT1(); } else { CP_WAIT0(); }
        __syncthreads();
        if (kt + 2 < 16) {
            const uint32_t la = sbase + (uint32_t)stl * (2 * GSTAGE_B);
            G_LOAD(la, la + GSTAGE_B, kt + 2);
        }
        const uint32_t aoff = sbase + (uint32_t)st * (2 * GSTAGE_B);
        const uint32_t boff = aoff + GSTAGE_B;

#pragma unroll
        for (int ks = 0; ks < 4; ks++) {
            uint32_t af[4][4];
#pragma unroll
            for (int mt = 0; mt < 4; mt++)
                ldsm4(af[mt][0], af[mt][1], af[mt][2], af[mt][3],
                      aoff + 4u * ((wm * 64 + mt * 16 + lrow) * GPAD2 + ks * 8 + lcol4));
#pragma unroll
            for (int np = 0; np < 2; np++) {
                uint32_t r0, r1, r2, r3;
                ldsm4(r0, r1, r2, r3,
                      boff + 4u * ((wn * 32 + np * 16 + lrow) * GPAD2 + ks * 8 + lcol4));
#pragma unroll
                for (int mt = 0; mt < 4; mt++) {
                    mma16(acc[mt][2 * np],     af[mt], r0, r2);
                    mma16(acc[mt][2 * np + 1], af[mt], r1, r3);
                }
            }
        }
        if (++st == 3) st = 0;
        if (++stl == 3) stl = 0;
    }

    // epilogue
#pragma unroll
    for (int mt = 0; mt < 4; mt++) {
        const int r0 = m0 + wm * 64 + mt * 16 + g;
#pragma unroll
        for (int nt = 0; nt < 4; nt++) {
            const int col = n0 + wn * 32 + nt * 8 + 2 * t;
            if (QKV) {
                const int mat = col >> 10, nl = col & 1023;
                const float* bias = (mat == 0 ? b0 : mat == 1 ? b1 : b2);
                const int h = nl >> 6, d = nl & 63;
                const float2 bv = *(const float2*)(bias + nl);
                const int b = r0 >> 11, s = r0 & 2047;
                float v0 = acc[mt][nt][0] + bv.x, v1 = acc[mt][nt][1] + bv.y;
                float v2 = acc[mt][nt][2] + bv.x, v3 = acc[mt][nt][3] + bv.y;
                if (mat == 0) {
                    v0 *= QSCALE; v1 *= QSCALE; v2 *= QSCALE; v3 *= QSCALE;
                    __half* p = hq + ((size_t)((b * 16 + h) * 2048 + s)) * 64 + d;
                    *(__half2*)p = __floats2half2_rn(v0, v1);
                    *(__half2*)(p + 8 * 64) = __floats2half2_rn(v2, v3);
                } else if (mat == 1) {
                    __half* p = hk + ((size_t)((b * 16 + h) * 2048 + s)) * 64 + d;
                    *(__half2*)p = __floats2half2_rn(v0, v1);
                    *(__half2*)(p + 8 * 64) = __floats2half2_rn(v2, v3);
                } else {
                    __half* vp = hvt + (size_t)(b * 16 + h) * 64 * S_LEN;
                    vp[(size_t)d * S_LEN + s]           = __float2half_rn(v0);
                    vp[(size_t)(d + 1) * S_LEN + s]     = __float2half_rn(v1);
                    vp[(size_t)d * S_LEN + s + 8]       = __float2half_rn(v2);
                    vp[(size_t)(d + 1) * S_LEN + s + 8] = __float2half_rn(v3);
                }
            } else {
                const float2 bv = *(const float2*)(b0 + col);
                const float2 x0 = *(const float2*)(xres + (size_t)r0 * 1024 + col);
                const float2 x1 = *(const float2*)(xres + (size_t)(r0 + 8) * 1024 + col);
                float* p = of + (size_t)r0 * 1024 + col;
                *(float2*)p = make_float2(acc[mt][nt][0] + bv.x + x0.x,
                                          acc[mt][nt][1] + bv.y + x0.y);
                *(float2*)(p + 8 * 1024) = make_float2(acc[mt][nt][2] + bv.x + x1.x,
                                                       acc[mt][nt][3] + bv.y + x1.y);
            }
        }
    }
}

// ======================= fp16 flash attention ==============================
// CTA: 128 queries, 8 warps. KV tiles of 128 keys (two 64-key halves).
// P in registers, l via ones-MMA, POFF folded into accumulator init.
#define APK  36
#define APV  68
#define QU   (128 * APK)
#define KU   (128 * APK)
#define VU   (64 * APV)
#define ATTN_SMEM ((QU + 2 * KU + 2 * VU) * 4)   // 90112 bytes

__global__ __launch_bounds__(256, 2) void attn_h(
    const __half* __restrict__ Q, const __half* __restrict__ K,
    const __half* __restrict__ Vt, __half* __restrict__ Ctx)
{
    extern __shared__ uint32_t smu[];
    const uint32_t uQ = smem_u32(smu);
    const uint32_t uK[2] = {uQ + 4u * QU, uQ + 4u * (QU + KU)};
    const uint32_t uV[2] = {uQ + 4u * (QU + 2 * KU), uQ + 4u * (QU + 2 * KU + VU)};

    const int bh = blockIdx.y;
    const int q0 = blockIdx.x * 128;
    const int tid = threadIdx.x;
    const int wid = tid >> 5, lane = tid & 31;
    const int g = lane >> 2, t = lane & 3;
    const int lrow  = (lane & 7) + ((lane >> 3) & 1) * 8;
    const int lcol4 = (lane >> 4) * 4;

    const __half* Qb = Q  + (size_t)bh * S_LEN * 64;
    const __half* Kb = K  + (size_t)bh * S_LEN * 64;
    const __half* Vb = Vt + (size_t)bh * 64 * S_LEN;

#define LOAD_K(st, kt) do { _Pragma("unroll") for (int i = 0; i < 4; i++) { \
    int j = tid + i * 256; int r = j >> 3, cq = j & 7;                      \
    cp16(uK[st] + (uint32_t)(r * APK + cq * 4) * 4,                         \
         Kb + (size_t)((kt) * 128 + r) * 64 + cq * 8); } } while (0)
#define LOAD_V(st, kt) do { _Pragma("unroll") for (int i = 0; i < 4; i++) { \
    int j = tid + i * 256; int r = j >> 4, cq = j & 15;                     \
    cp16(uV[st] + (uint32_t)(r * APV + cq * 4) * 4,                         \
         Vb + (size_t)r * S_LEN + (kt) * 128 + cq * 8); } } while (0)

    // prologue: Q + K0 + V0
#pragma unroll
    for (int i = 0; i < 4; i++) {
        int j = tid + i * 256; int r = j >> 3, cq = j & 7;
        cp16(uQ + (uint32_t)(r * APK + cq * 4) * 4, Qb + (size_t)(q0 + r) * 64 + cq * 8);
    }
    LOAD_K(0, 0); LOAD_V(0, 0); CP_COMMIT();
    CP_WAIT0();
    __syncthreads();

    const int rbase = wid * 16 + g;

    uint32_t qf[4][4];
#pragma unroll
    for (int ks = 0; ks < 4; ks++)
        ldsm4(qf[ks][0], qf[ks][1], qf[ks][2], qf[ks][3],
              uQ + 4u * ((wid * 16 + lrow) * APK + ks * 8 + lcol4));

    float lacc[4] = {0.f, 0.f, 0.f, 0.f};
    float oacc[8][4];
#pragma unroll
    for (int i = 0; i < 8; i++)
#pragma unroll
        for (int r = 0; r < 4; r++) oacc[i][r] = 0.f;

    for (int kt = 0; kt < 16; kt++) {
        const int st = kt & 1;
        if (kt > 0) { CP_WAIT0(); __syncthreads(); }
        if (kt < 15) { LOAD_K(st ^ 1, kt + 1); LOAD_V(st ^ 1, kt + 1); CP_COMMIT(); }

#pragma unroll
        for (int hf = 0; hf < 2; hf++) {
            float sacc[8][4];
#pragma unroll
            for (int i = 0; i < 8; i++)
#pragma unroll
                for (int r = 0; r < 4; r++) sacc[i][r] = -POFF;

#pragma unroll
            for (int ks = 0; ks < 4; ks++) {
#pragma unroll
                for (int np = 0; np < 4; np++) {
                    uint32_t r0, r1, r2, r3;
                    ldsm4(r0, r1, r2, r3,
                          uK[st] + 4u * ((hf * 64 + np * 16 + lrow) * APK + ks * 8 + lcol4));
                    mma16(sacc[2 * np],     qf[ks], r0, r2);
                    mma16(sacc[2 * np + 1], qf[ks], r1, r3);
                }
            }

#pragma unroll
            for (int ks = 0; ks < 4; ks++) {
                uint32_t pf[4];
                pf[0] = pexp2(sacc[2 * ks][0],     sacc[2 * ks][1]);
                pf[1] = pexp2(sacc[2 * ks][2],     sacc[2 * ks][3]);
                pf[2] = pexp2(sacc[2 * ks + 1][0], sacc[2 * ks + 1][1]);
                pf[3] = pexp2(sacc[2 * ks + 1][2], sacc[2 * ks + 1][3]);

                mma16(lacc, pf, ONES2, ONES2);

#pragma unroll
                for (int np = 0; np < 4; np++) {
                    uint32_t r0, r1, r2, r3;
                    ldsm4(r0, r1, r2, r3,
                          uV[st] + 4u * ((np * 16 + lrow) * APV + hf * 32 + ks * 8 + lcol4));
                    mma16(oacc[2 * np],     pf, r0, r2);
                    mma16(oacc[2 * np + 1], pf, r1, r3);
                }
            }
        }
    }

    const float inv0 = 1.f / lacc[0], inv1 = 1.f / lacc[2];
    const int b = bh >> 4, h = bh & 15;
    const int row0 = q0 + rbase;
    __half* base0 = Ctx + ((size_t)(b * 2048 + row0)) * 1024 + h * 64;
#pragma unroll
    for (int nt = 0; nt < 8; nt++) {
        const int col = nt * 8 + 2 * t;
        *(__half2*)(base0 + col) = __floats2half2_rn(oacc[nt][0] * inv0, oacc[nt][1] * inv0);
        *(__half2*)(base0 + 8 * 1024 + col) = __floats2half2_rn(oacc[nt][2] * inv1,
                                                                oacc[nt][3] * inv1);
    }
}

// ======================= fused prep: weights transpose + x convert ========
__global__ __launch_bounds__(256) void prep_all(
    const float* __restrict__ Wq, const float* __restrict__ Wk,
    const float* __restrict__ Wv, const float* __restrict__ Wo,
    const float* __restrict__ x,
    __half* __restrict__ Wh, __half* __restrict__ Woh, __half* __restrict__ xh)
{
    const int z = blockIdx.z;
    const int tx = threadIdx.x, ty = threadIdx.y;   // 32 x 8
    if (z == 4) {
        const int tl = (blockIdx.y * 32 + blockIdx.x) * 256 + ty * 32 + tx;
#pragma unroll
        for (int k = 0; k < 4; k++) {
            const int i = tl + k * 262144;
            float4 v = ((const float4*)x)[i];
            ((__half2*)xh)[2 * i]     = __floats2half2_rn(v.x, v.y);
            ((__half2*)xh)[2 * i + 1] = __floats2half2_rn(v.z, v.w);
        }
        return;
    }
    __shared__ float tb[32][33];
    const float* src = (z == 0) ? Wq : (z == 1) ? Wk : (z == 2) ? Wv : Wo;
    __half* dst = (z < 3) ? (Wh + (size_t)z * D_MOD * D_MOD) : Woh;
    const int k0 = blockIdx.x * 32, n0 = blockIdx.y * 32;
#pragma unroll
    for (int i = 0; i < 4; i++)
        tb[ty + i * 8][tx] = src[(size_t)(k0 + ty + i * 8) * D_MOD + n0 + tx];
    __syncthreads();
#pragma unroll
    for (int i = 0; i < 4; i++)
        dst[(size_t)(n0 + ty + i * 8) * D_MOD + k0 + tx] = __float2half_rn(tb[tx][ty + i * 8]);
}

// ---------------- LayerNorm (input h already includes residual) -----------
__global__ __launch_bounds__(256) void ln_kernel(
    const float* __restrict__ hin,
    const float* __restrict__ gamma, const float* __restrict__ beta,
    float* __restrict__ out)
{
    const int row = blockIdx.x;
    const int tid = threadIdx.x;

    const float4 h = ((const float4*)(hin + (size_t)row * D_MOD))[tid];

    float sum = h.x + h.y + h.z + h.w;
    float ssq = h.x * h.x + h.y * h.y + h.z * h.z + h.w * h.w;
#pragma unroll
    for (int o = 16; o > 0; o >>= 1) {
        sum += __shfl_xor_sync(0xffffffffu, sum, o);
        ssq += __shfl_xor_sync(0xffffffffu, ssq, o);
    }
    __shared__ float rs[8], rq[8];
    const int warp = tid >> 5, lane = tid & 31;
    if (lane == 0) { rs[warp] = sum; rq[warp] = ssq; }
    __syncthreads();
    float ts = 0.f, tq = 0.f;
#pragma unroll
    for (int i = 0; i < 8; i++) { ts += rs[i]; tq += rq[i]; }

    const float mu   = ts * (1.f / (float)D_MOD);
    const float var  = tq * (1.f / (float)D_MOD) - mu * mu;
    const float rstd = rsqrtf(var + 1e-5f);

    const float4 gg = ((const float4*)gamma)[tid];
    const float4 bb = ((const float4*)beta)[tid];
    float4 o;
    o.x = (h.x - mu) * rstd * gg.x + bb.x;
    o.y = (h.y - mu) * rstd * gg.y + bb.y;
    o.z = (h.z - mu) * rstd * gg.z + bb.z;
    o.w = (h.w - mu) * rstd * gg.w + bb.w;
    ((float4*)(out + (size_t)row * D_MOD))[tid] = o;
}

// ---------------- launch ----------------------------------------------------
extern "C" void kernel_launch(void* const* d_in, const int* in_sizes, int n_in,
                              void* d_out, int out_size)
{
    const float* x  = (const float*)d_in[0];
    const float* Wq = (const float*)d_in[1];
    const float* bq = (const float*)d_in[2];
    const float* Wk = (const float*)d_in[3];
    const float* bk = (const float*)d_in[4];
    const float* Wv = (const float*)d_in[5];
    const float* bv = (const float*)d_in[6];
    const float* Wo = (const float*)d_in[7];
    const float* bo = (const float*)d_in[8];
    const float* ga = (const float*)d_in[9];
    const float* be = (const float*)d_in[10];
    float* out = (float*)d_out;

    __half *Xh, *Wh, *Woh, *Qp, *Kp, *Vtp, *Ch;
    float *Pp;
    cudaGetSymbolAddress((void**)&Xh,  g_xh);
    cudaGetSymbolAddress((void**)&Wh,  g_Wh);
    cudaGetSymbolAddress((void**)&Woh, g_Woh);
    cudaGetSymbolAddress((void**)&Qp,  g_Q);
    cudaGetSymbolAddress((void**)&Kp,  g_K);
    cudaGetSymbolAddress((void**)&Vtp, g_Vt);
    cudaGetSymbolAddress((void**)&Ch,  g_ctxh);
    cudaGetSymbolAddress((void**)&Pp,  g_prj);

    cudaFuncSetAttribute(attn_h, cudaFuncAttributeMaxDynamicSharedMemorySize, ATTN_SMEM);
    cudaFuncSetAttribute(gemm_h<1>, cudaFuncAttributeMaxDynamicSharedMemorySize, GEMM_SMEM);
    cudaFuncSetAttribute(gemm_h<0>, cudaFuncAttributeMaxDynamicSharedMemorySize, GEMM_SMEM);

    prep_all<<<dim3(32, 32, 5), dim3(32, 8)>>>(Wq, Wk, Wv, Wo, x, Wh, Woh, Xh);

    gemm_h<1><<<dim3(24, 32), 256, GEMM_SMEM>>>(Xh, Wh, bq, bk, bv, Qp, Kp, Vtp,
                                                nullptr, nullptr);

    attn_h<<<dim3(S_LEN / 128, NBH), 256, ATTN_SMEM>>>(Qp, Kp, Vtp, Ch);

    gemm_h<0><<<dim3(8, 32), 256, GEMM_SMEM>>>(Ch, Woh, bo, bo, bo,
                                               nullptr, nullptr, nullptr, x, Pp);

    ln_kernel<<<ROWS, 256>>>(Pp, ga, be, out);
}